// round 7
// baseline (speedup 1.0000x reference)
#include <cuda_runtime.h>
#include <cuda_bf16.h>
#include <cstdint>

// ---------------- scratch (__device__ globals; no allocation allowed) -------
__device__ __nv_bfloat16 g_xs_hi[4096 * 1024];        // split of x
__device__ __nv_bfloat16 g_xs_lo[4096 * 1024];
__device__ __nv_bfloat16 g_ks_hi[4096 * 1024];        // split of K projection
__device__ __nv_bfloat16 g_ks_lo[4096 * 1024];
__device__ __nv_bfloat16 g_att_hi[4096 * 1024];       // split of attention out
__device__ __nv_bfloat16 g_att_lo[4096 * 1024];
__device__ __nv_bfloat16 g_wk_hi[1024 * 1024];        // W_attn K-slice, [n][k]
__device__ __nv_bfloat16 g_wk_lo[1024 * 1024];
__device__ __nv_bfloat16 g_wp_hi[1024 * 1024];        // W_proj, [n][k]
__device__ __nv_bfloat16 g_wp_lo[1024 * 1024];

// ---------------- PTX helpers (all compute_103-safe) ------------------------
__device__ __forceinline__ float fast_exp2(float x) {
    float y; asm("ex2.approx.ftz.f32 %0, %1;" : "=f"(y) : "f"(x)); return y;
}
__device__ __forceinline__ uint32_t smem_u32(const void* p) {
    uint32_t a;
    asm("{ .reg .u64 t; cvta.to.shared.u64 t, %1; cvt.u32.u64 %0, t; }" : "=r"(a) : "l"(p));
    return a;
}
__device__ __forceinline__ void cp_async16(uint32_t dst, const void* src) {
    asm volatile("cp.async.cg.shared.global [%0], [%1], 16;" :: "r"(dst), "l"(src));
}
__device__ __forceinline__ void cp_commit() {
    asm volatile("cp.async.commit_group;" ::: "memory");
}
__device__ __forceinline__ void cp_wait1() {
    asm volatile("cp.async.wait_group 1;" ::: "memory");
}
__device__ __forceinline__ void cp_wait0() {
    asm volatile("cp.async.wait_group 0;" ::: "memory");
}
__device__ __forceinline__ void ldsm4(uint32_t& r0, uint32_t& r1, uint32_t& r2,
                                      uint32_t& r3, uint32_t addr) {
    asm volatile("ldmatrix.sync.aligned.m8n8.x4.shared.b16 {%0,%1,%2,%3}, [%4];"
                 : "=r"(r0), "=r"(r1), "=r"(r2), "=r"(r3) : "r"(addr));
}
__device__ __forceinline__ void ldsm4t(uint32_t& r0, uint32_t& r1, uint32_t& r2,
                                       uint32_t& r3, uint32_t addr) {
    asm volatile("ldmatrix.sync.aligned.m8n8.x4.trans.shared.b16 {%0,%1,%2,%3}, [%4];"
                 : "=r"(r0), "=r"(r1), "=r"(r2), "=r"(r3) : "r"(addr));
}
__device__ __forceinline__ void mma_bf16(float* c, const uint32_t* a,
                                         uint32_t b0, uint32_t b1) {
    asm volatile(
        "mma.sync.aligned.m16n8k16.row.col.f32.bf16.bf16.f32 "
        "{%0,%1,%2,%3}, {%4,%5,%6,%7}, {%8,%9}, {%0,%1,%2,%3};"
        : "+f"(c[0]), "+f"(c[1]), "+f"(c[2]), "+f"(c[3])
        : "r"(a[0]), "r"(a[1]), "r"(a[2]), "r"(a[3]), "r"(b0), "r"(b1));
}
__device__ __forceinline__ uint32_t pack_bf16x2(float lo, float hi) {
    __nv_bfloat162 r = __float22bfloat162_rn(make_float2(lo, hi));
    return *(uint32_t*)&r;
}

// ---------------- prep: split x into bf16 hi/lo -----------------------------
__global__ __launch_bounds__(256) void splitX_kernel(
    const float* __restrict__ X,
    __nv_bfloat16* __restrict__ Hi, __nv_bfloat16* __restrict__ Lo)
{
    int i = blockIdx.x * 256 + threadIdx.x;
    float4 v = ((const float4*)X)[i];
    __nv_bfloat16 h0 = __float2bfloat16(v.x), h1 = __float2bfloat16(v.y);
    __nv_bfloat16 h2 = __float2bfloat16(v.z), h3 = __float2bfloat16(v.w);
    ((__nv_bfloat162*)Hi)[i * 2]     = __halves2bfloat162(h0, h1);
    ((__nv_bfloat162*)Hi)[i * 2 + 1] = __halves2bfloat162(h2, h3);
    ((__nv_bfloat162*)Lo)[i * 2]     = __halves2bfloat162(
        __float2bfloat16(v.x - __bfloat162float(h0)),
        __float2bfloat16(v.y - __bfloat162float(h1)));
    ((__nv_bfloat162*)Lo)[i * 2 + 1] = __halves2bfloat162(
        __float2bfloat16(v.z - __bfloat162float(h2)),
        __float2bfloat16(v.w - __bfloat162float(h3)));
}

// ---------------- prep: transpose W[k][n] -> [n][k] + split -----------------
__global__ void splitW_kernel(const float* __restrict__ W, int ldw,
                              __nv_bfloat16* __restrict__ Ohi,
                              __nv_bfloat16* __restrict__ Olo)
{
    __shared__ float t[32][33];
    int tx = threadIdx.x, ty = threadIdx.y;
    int n0 = blockIdx.x * 32, k0 = blockIdx.y * 32;
#pragma unroll
    for (int p = 0; p < 4; p++)
        t[ty + 8 * p][tx] = W[(size_t)(k0 + ty + 8 * p) * ldw + n0 + tx];
    __syncthreads();
#pragma unroll
    for (int p = 0; p < 4; p++) {
        float v = t[tx][ty + 8 * p];
        __nv_bfloat16 h = __float2bfloat16(v);
        size_t o = (size_t)(n0 + ty + 8 * p) * 1024 + k0 + tx;
        Ohi[o] = h;
        Olo[o] = __float2bfloat16(v - __bfloat162float(h));
    }
}

// ---------------- tensor-core GEMM via mma.sync (bf16 3-split) --------------
// Tile: M=128, N=64, BK=64, 8 warps (4m x 2n, warp 32x32), double-buffered.
// Stage layout: Ahi[128][72] Alo Bhi[64][72] Blo (rows padded to 144 B).
#define ROWB 144
#define GA_HI 0
#define GA_LO 18432
#define GB_HI 36864
#define GB_LO 46080
#define STAGE2 55296

__global__ __launch_bounds__(256, 2) void gemm_mma(
    const __nv_bfloat16* __restrict__ Ahi, const __nv_bfloat16* __restrict__ Alo,
    const __nv_bfloat16* __restrict__ Bhi, const __nv_bfloat16* __restrict__ Blo,
    const float* __restrict__ bias, float* __restrict__ C,
    __nv_bfloat16* __restrict__ Chi, __nv_bfloat16* __restrict__ Clo)
{
    extern __shared__ char smem[];
    const uint32_t sb = smem_u32(smem);
    const int tid = threadIdx.x;
    const int wid = tid >> 5;
    const int lane = tid & 31;
    const int wm = wid >> 1;        // 0..3, 32 rows each
    const int wn = wid & 1;         // 0..1, 32 cols each
    const int m0 = blockIdx.y * 128, n0 = blockIdx.x * 64;

    const int lrow = tid >> 3;      // A: 0..31 (+32p), B: 0..31 (+32p)
    const int lkc = tid & 7;

    const uint32_t a_off = (uint32_t)((wm * 32 + (lane & 15)) * ROWB + (lane >> 4) * 16);
    const uint32_t b_off = (uint32_t)((wn * 32 + (lane & 15)) * ROWB + (lane >> 4) * 16);

    float acc[2][4][4];
#pragma unroll
    for (int i = 0; i < 2; i++)
#pragma unroll
        for (int j = 0; j < 4; j++)
#pragma unroll
            for (int r = 0; r < 4; r++) acc[i][j][r] = 0.0f;

    // prologue: chunk 0 -> stage 0
#pragma unroll
    for (int q = 0; q < 4; q++) {
        int row = lrow + q * 32;
        cp_async16(sb + GA_HI + row * ROWB + lkc * 16,
                   (const char*)Ahi + (size_t)(m0 + row) * 2048 + lkc * 16);
        cp_async16(sb + GA_LO + row * ROWB + lkc * 16,
                   (const char*)Alo + (size_t)(m0 + row) * 2048 + lkc * 16);
    }
#pragma unroll
    for (int q = 0; q < 2; q++) {
        int row = lrow + q * 32;
        cp_async16(sb + GB_HI + row * ROWB + lkc * 16,
                   (const char*)Bhi + (size_t)(n0 + row) * 2048 + lkc * 16);
        cp_async16(sb + GB_LO + row * ROWB + lkc * 16,
                   (const char*)Blo + (size_t)(n0 + row) * 2048 + lkc * 16);
    }
    cp_commit();

    for (int c = 0; c < 16; c++) {
        const uint32_t st = (uint32_t)(c & 1) * STAGE2;
        if (c + 1 < 16) {
            const uint32_t st2 = (uint32_t)((c + 1) & 1) * STAGE2;
            const size_t ko = (size_t)(c + 1) * 128;
#pragma unroll
            for (int q = 0; q < 4; q++) {
                int row = lrow + q * 32;
                cp_async16(st2 + sb + GA_HI + row * ROWB + lkc * 16,
                           (const char*)Ahi + (size_t)(m0 + row) * 2048 + ko + lkc * 16);
                cp_async16(st2 + sb + GA_LO + row * ROWB + lkc * 16,
                           (const char*)Alo + (size_t)(m0 + row) * 2048 + ko + lkc * 16);
            }
#pragma unroll
            for (int q = 0; q < 2; q++) {
                int row = lrow + q * 32;
                cp_async16(st2 + sb + GB_HI + row * ROWB + lkc * 16,
                           (const char*)Bhi + (size_t)(n0 + row) * 2048 + ko + lkc * 16);
                cp_async16(st2 + sb + GB_LO + row * ROWB + lkc * 16,
                           (const char*)Blo + (size_t)(n0 + row) * 2048 + ko + lkc * 16);
            }
            cp_commit();
            cp_wait1();
        } else {
            cp_wait0();
        }
        __syncthreads();

#pragma unroll
        for (int kk = 0; kk < 4; kk++) {
            uint32_t bh[2][4], bl[2][4];
#pragma unroll
            for (int p = 0; p < 2; p++) {
                uint32_t addr = st + sb + b_off + (uint32_t)(p * 16 * ROWB) + kk * 32;
                ldsm4(bh[p][0], bh[p][1], bh[p][2], bh[p][3], addr + GB_HI);
                ldsm4(bl[p][0], bl[p][1], bl[p][2], bl[p][3], addr + GB_LO);
            }
#pragma unroll
            for (int mf = 0; mf < 2; mf++) {
                uint32_t ah[4], al[4];
                uint32_t addr = st + sb + a_off + (uint32_t)(mf * 16 * ROWB) + kk * 32;
                ldsm4(ah[0], ah[1], ah[2], ah[3], addr + GA_HI);
                ldsm4(al[0], al[1], al[2], al[3], addr + GA_LO);
#pragma unroll
                for (int nf = 0; nf < 4; nf++) {
                    const int p = nf >> 1, hh = nf & 1;
                    mma_bf16(acc[mf][nf], ah, bh[p][hh], bh[p][2 + hh]);
                    mma_bf16(acc[mf][nf], ah, bl[p][hh], bl[p][2 + hh]);
                    mma_bf16(acc[mf][nf], al, bh[p][hh], bh[p][2 + hh]);
                }
            }
        }
        __syncthreads();
    }

    // epilogue
#pragma unroll
    for (int nf = 0; nf < 4; nf++) {
        int n = n0 + wn * 32 + nf * 8 + (lane & 3) * 2;
        float2 bv = *(const float2*)(bias + n);
#pragma unroll
        for (int mf = 0; mf < 2; mf++) {
            int m = m0 + wm * 32 + mf * 16 + (lane >> 2);
            float2 o0 = {acc[mf][nf][0] + bv.x, acc[mf][nf][1] + bv.y};
            float2 o1 = {acc[mf][nf][2] + bv.x, acc[mf][nf][3] + bv.y};
            if (Chi) {
                size_t i0 = (size_t)m * 1024 + n;
                size_t i1 = (size_t)(m + 8) * 1024 + n;
                __nv_bfloat16 a0 = __float2bfloat16(o0.x), a1 = __float2bfloat16(o0.y);
                __nv_bfloat16 b0 = __float2bfloat16(o1.x), b1 = __float2bfloat16(o1.y);
                *(__nv_bfloat162*)(Chi + i0) = __halves2bfloat162(a0, a1);
                *(__nv_bfloat162*)(Chi + i1) = __halves2bfloat162(b0, b1);
                *(__nv_bfloat162*)(Clo + i0) = __halves2bfloat162(
                    __float2bfloat16(o0.x - __bfloat162float(a0)),
                    __float2bfloat16(o0.y - __bfloat162float(a1)));
                *(__nv_bfloat162*)(Clo + i1) = __halves2bfloat162(
                    __float2bfloat16(o1.x - __bfloat162float(b0)),
                    __float2bfloat16(o1.y - __bfloat162float(b1)));
            } else {
                *(float2*)(C + (size_t)m * 1024 + n) = o0;
                *(float2*)(C + (size_t)(m + 8) * 1024 + n) = o1;
            }
        }
    }
}

// ---------------- FA2-style attention on tensor cores -----------------------
// Reads pre-split bf16 K (hi/lo). Q tile == K rows (scale folded in softmax).
// smem: Qhi/Qlo [128][64] + double-buffered Khi/Klo per stage.
#define AQ_HI 0
#define AQ_LO 18432
#define AK0   36864         // stage p at AK0 + p*36864; lo at +18432
#define AKST  36864
#define ATTN_SMEM_B (36864 + 2 * 36864)

__global__ __launch_bounds__(256) void attn_mma(
    const __nv_bfloat16* __restrict__ Khi, const __nv_bfloat16* __restrict__ Klo,
    __nv_bfloat16* __restrict__ OutHi, __nv_bfloat16* __restrict__ OutLo)
{
    extern __shared__ char smem[];
    const uint32_t sb = smem_u32(smem);
    const int tid = threadIdx.x;
    const int wid = tid >> 5;
    const int lane = tid & 31;
    const int g = lane >> 2;
    const int tq = lane & 3;
    const int b = blockIdx.y >> 4;
    const int h = blockIdx.y & 15;
    const int q0 = blockIdx.x * 128;

    const char* KbH = (const char*)Khi + (size_t)b * 2048 * 2048 + h * 128;
    const char* KbL = (const char*)Klo + (size_t)b * 2048 * 2048 + h * 128;
    const float SC = 0.125f * 1.4426950408889634f;  // 1/sqrt(64) * log2(e)

    const int lrow = tid >> 1;      // 0..127 (2 units of 16B per row: 64 bf16)
    const int lkc = tid & 1;

    // prologue: Q tile + K tile 0 (group 0)
#pragma unroll
    for (int q = 0; q < 2; q++) {
        // Q rows: 128 rows x 8 c16 -> use 256 threads x 4
        int u = tid + q * 256;
        int row = u >> 2, c = (u & 3) * 2;  // two 16B units per iter
        cp_async16(sb + AQ_HI + row * ROWB + c * 16,
                   KbH + (size_t)(q0 + row) * 2048 + c * 16);
        cp_async16(sb + AQ_HI + row * ROWB + (c + 1) * 16,
                   KbH + (size_t)(q0 + row) * 2048 + (c + 1) * 16);
        cp_async16(sb + AQ_LO + row * ROWB + c * 16,
                   KbL + (size_t)(q0 + row) * 2048 + c * 16);
        cp_async16(sb + AQ_LO + row * ROWB + (c + 1) * 16,
                   KbL + (size_t)(q0 + row) * 2048 + (c + 1) * 16);
    }
#pragma unroll
    for (int q = 0; q < 2; q++) {
        int u = tid + q * 256;
        int row = u >> 2, c = (u & 3) * 2;
        cp_async16(sb + AK0 + row * ROWB + c * 16,
                   KbH + (size_t)row * 2048 + c * 16);
        cp_async16(sb + AK0 + row * ROWB + (c + 1) * 16,
                   KbH + (size_t)row * 2048 + (c + 1) * 16);
        cp_async16(sb + AK0 + 18432 + row * ROWB + c * 16,
                   KbL + (size_t)row * 2048 + c * 16);
        cp_async16(sb + AK0 + 18432 + row * ROWB + (c + 1) * 16,
                   KbL + (size_t)row * 2048 + (c + 1) * 16);
    }
    cp_commit();

    float m0 = -1e30f, m1 = -1e30f, l0 = 0.0f, l1 = 0.0f;
    float o[8][4];
#pragma unroll
    for (int nf = 0; nf < 8; nf++)
#pragma unroll
        for (int r = 0; r < 4; r++) o[nf][r] = 0.0f;

    const uint32_t qa_off = (uint32_t)((wid * 16 + (lane & 15)) * ROWB + (lane >> 4) * 16);
    const uint32_t kb_row = (uint32_t)((lane & 15) * ROWB + (lane >> 4) * 16);

    for (int kt = 0; kt < 16; kt++) {
        const uint32_t st = sb + AK0 + (uint32_t)(kt & 1) * AKST;
        if (kt + 1 < 16) {
            const uint32_t st2 = sb + AK0 + (uint32_t)((kt + 1) & 1) * AKST;
            const size_t j0 = (size_t)(kt + 1) * 128;
#pragma unroll
            for (int q = 0; q < 2; q++) {
                int u = tid + q * 256;
                int row = u >> 2, c = (u & 3) * 2;
                cp_async16(st2 + row * ROWB + c * 16,
                           KbH + (j0 + row) * 2048 + c * 16);
                cp_async16(st2 + row * ROWB + (c + 1) * 16,
                           KbH + (j0 + row) * 2048 + (c + 1) * 16);
                cp_async16(st2 + 18432 + row * ROWB + c * 16,
                           KbL + (j0 + row) * 2048 + c * 16);
                cp_async16(st2 + 18432 + row * ROWB + (c + 1) * 16,
                           KbL + (j0 + row) * 2048 + (c + 1) * 16);
            }
            cp_commit();
            cp_wait1();
        } else {
            cp_wait0();
        }
        __syncthreads();

        // ---- S = Q K^T (raw, unscaled) ----
        float s[16][4];
#pragma unroll
        for (int nf = 0; nf < 16; nf++)
#pragma unroll
            for (int r = 0; r < 4; r++) s[nf][r] = 0.0f;

#pragma unroll
        for (int kk = 0; kk < 4; kk++) {
            uint32_t qh[4], ql[4];
            ldsm4(qh[0], qh[1], qh[2], qh[3], sb + AQ_HI + qa_off + kk * 32);
            ldsm4(ql[0], ql[1], ql[2], ql[3], sb + AQ_LO + qa_off + kk * 32);
#pragma unroll
            for (int nb = 0; nb < 8; nb++) {
                uint32_t kh[4], kl[4];
                uint32_t addr = st + kb_row + (uint32_t)(nb * 16 * ROWB) + kk * 32;
                ldsm4(kh[0], kh[1], kh[2], kh[3], addr);
                ldsm4(kl[0], kl[1], kl[2], kl[3], addr + 18432);
#pragma unroll
                for (int hh = 0; hh < 2; hh++) {
                    mma_bf16(s[2 * nb + hh], qh, kh[hh], kh[2 + hh]);
                    mma_bf16(s[2 * nb + hh], qh, kl[hh], kl[2 + hh]);
                    mma_bf16(s[2 * nb + hh], ql, kh[hh], kh[2 + hh]);
                }
            }
        }

        // ---- online softmax (scale SC folded in) ----
        float mx0 = -1e30f, mx1 = -1e30f;
#pragma unroll
        for (int nf = 0; nf < 16; nf++) {
            mx0 = fmaxf(mx0, fmaxf(s[nf][0], s[nf][1]));
            mx1 = fmaxf(mx1, fmaxf(s[nf][2], s[nf][3]));
        }
        mx0 = fmaxf(mx0, __shfl_xor_sync(0xffffffffu, mx0, 1));
        mx0 = fmaxf(mx0, __shfl_xor_sync(0xffffffffu, mx0, 2));
        mx1 = fmaxf(mx1, __shfl_xor_sync(0xffffffffu, mx1, 1));
        mx1 = fmaxf(mx1, __shfl_xor_sync(0xffffffffu, mx1, 2));
        float mn0 = fmaxf(m0, mx0), mn1 = fmaxf(m1, mx1);
        float c0 = fast_exp2((m0 - mn0) * SC), c1 = fast_exp2((m1 - mn1) * SC);
        m0 = mn0; m1 = mn1;
        l0 *= c0; l1 *= c1;
#pragma unroll
        for (int nf = 0; nf < 8; nf++) {
            o[nf][0] *= c0; o[nf][1] *= c0;
            o[nf][2] *= c1; o[nf][3] *= c1;
        }
        const float b0s = -mn0 * SC, b1s = -mn1 * SC;
        float rs0 = 0.0f, rs1 = 0.0f;
#pragma unroll
        for (int nf = 0; nf < 16; nf++) {
            s[nf][0] = fast_exp2(fmaf(s[nf][0], SC, b0s));
            s[nf][1] = fast_exp2(fmaf(s[nf][1], SC, b0s));
            s[nf][2] = fast_exp2(fmaf(s[nf][2], SC, b1s));
            s[nf][3] = fast_exp2(fmaf(s[nf][3], SC, b1s));
            rs0 += s[nf][0] + s[nf][1];
            rs1 += s[nf][2] + s[nf][3];
        }
        rs0 += __shfl_xor_sync(0xffffffffu, rs0, 1);
        rs0 += __shfl_xor_sync(0xffffffffu, rs0, 2);
        rs1 += __shfl_xor_sync(0xffffffffu, rs1, 1);
        rs1 += __shfl_xor_sync(0xffffffffu, rs1, 2);
        l0 += rs0; l1 += rs1;

        // ---- O += P V (P hi/lo from registers, V via ldsm.trans) ----
#pragma unroll
        for (int t = 0; t < 8; t++) {
            uint32_t ph[4], pl[4];
#pragma unroll
            for (int half = 0; half < 2; half++) {
                const int nf = 2 * t + half;
                float h00f = s[nf][0], h01f = s[nf][1];
                float h10f = s[nf][2], h11f = s[nf][3];
                uint32_t hi0 = pack_bf16x2(h00f, h01f);
                uint32_t hi1 = pack_bf16x2(h10f, h11f);
                __nv_bfloat162 hv0 = *(__nv_bfloat162*)&hi0;
                __nv_bfloat162 hv1 = *(__nv_bfloat162*)&hi1;
                uint32_t lo0 = pack_bf16x2(h00f - __bfloat162float(hv0.x),
                                           h01f - __bfloat162float(hv0.y));
                uint32_t lo1 = pack_bf16x2(h10f - __bfloat162float(hv1.x),
                                           h11f - __bfloat162float(hv1.y));
                ph[2 * half] = hi0; ph[2 * half + 1] = hi1;
                pl[2 * half] = lo0; pl[2 * half + 1] = lo1;
            }
#pragma unroll
            for (int nb = 0; nb < 4; nb++) {
                uint32_t vh[4], vl[4];
                uint32_t addr = st + kb_row + (uint32_t)(t * 16 * ROWB) + nb * 32;
                ldsm4t(vh[0], vh[1], vh[2], vh[3], addr);
                ldsm4t(vl[0], vl[1], vl[2], vl[3], addr + 18432);
#pragma unroll
                for (int hh = 0; hh < 2; hh++) {
                    mma_bf16(o[2 * nb + hh], ph, vh[2 * hh], vh[2 * hh + 1]);
                    mma_bf16(o[2 * nb + hh], pl, vh[2 * hh], vh[2 * hh + 1]);
                    mma_bf16(o[2 * nb + hh], ph, vl[2 * hh], vl[2 * hh + 1]);
                }
            }
        }
        __syncthreads();
    }

    // ---- epilogue: normalize and write bf16 hi/lo split ----
    float inv0 = 1.0f / l0, inv1 = 1.0f / l1;
    int mr0 = q0 + wid * 16 + g;
#pragma unroll
    for (int nf = 0; nf < 8; nf++) {
        int d = h * 64 + nf * 8 + tq * 2;
        size_t i0 = ((size_t)b * 2048 + mr0) * 1024 + d;
        size_t i1 = i0 + 8 * 1024;
        float v00 = o[nf][0] * inv0, v01 = o[nf][1] * inv0;
        float v10 = o[nf][2] * inv1, v11 = o[nf][3] * inv1;
        __nv_bfloat16 a0 = __float2bfloat16(v00), a1 = __float2bfloat16(v01);
        __nv_bfloat16 b0 = __float2bfloat16(v10), b1 = __float2bfloat16(v11);
        *(__nv_bfloat162*)(OutHi + i0) = __halves2bfloat162(a0, a1);
        *(__nv_bfloat162*)(OutHi + i1) = __halves2bfloat162(b0, b1);
        *(__nv_bfloat162*)(OutLo + i0) = __halves2bfloat162(
            __float2bfloat16(v00 - __bfloat162float(a0)),
            __float2bfloat16(v01 - __bfloat162float(a1)));
        *(__nv_bfloat162*)(OutLo + i1) = __halves2bfloat162(
            __float2bfloat16(v10 - __bfloat162float(b0)),
            __float2bfloat16(v11 - __bfloat162float(b1)));
    }
}

// ---------------------------------------------------------------------------
extern "C" void kernel_launch(void* const* d_in, const int* in_sizes, int n_in,
                              void* d_out, int out_size) {
    const float* x      = (const float*)d_in[0];  // (2, 2048, 1024)
    const float* W_attn = (const float*)d_in[1];  // (1024, 3072)
    const float* b_attn = (const float*)d_in[2];  // (3072,)
    const float* W_proj = (const float*)d_in[3];  // (1024, 1024)
    const float* b_proj = (const float*)d_in[4];  // (1024,)
    float* out = (float*)d_out;                   // (2, 2048, 1024)

    __nv_bfloat16 *xs_hi, *xs_lo, *ks_hi, *ks_lo, *att_hi, *att_lo;
    __nv_bfloat16 *wk_hi, *wk_lo, *wp_hi, *wp_lo;
    cudaGetSymbolAddress((void**)&xs_hi, g_xs_hi);
    cudaGetSymbolAddress((void**)&xs_lo, g_xs_lo);
    cudaGetSymbolAddress((void**)&ks_hi, g_ks_hi);
    cudaGetSymbolAddress((void**)&ks_lo, g_ks_lo);
    cudaGetSymbolAddress((void**)&att_hi, g_att_hi);
    cudaGetSymbolAddress((void**)&att_lo, g_att_lo);
    cudaGetSymbolAddress((void**)&wk_hi, g_wk_hi);
    cudaGetSymbolAddress((void**)&wk_lo, g_wk_lo);
    cudaGetSymbolAddress((void**)&wp_hi, g_wp_hi);
    cudaGetSymbolAddress((void**)&wp_lo, g_wp_lo);

    const int GEMM_SMEM = 2 * STAGE2;  // 110592
    cudaFuncSetAttribute(gemm_mma,
                         cudaFuncAttributeMaxDynamicSharedMemorySize, GEMM_SMEM);
    cudaFuncSetAttribute(attn_mma,
                         cudaFuncAttributeMaxDynamicSharedMemorySize, ATTN_SMEM_B);

    // Prep: bf16 splits of inputs
    splitX_kernel<<<4096, 256>>>(x, xs_hi, xs_lo);
    splitW_kernel<<<dim3(32, 32), dim3(32, 8)>>>(W_attn + 1024, 3072, wk_hi, wk_lo);
    splitW_kernel<<<dim3(32, 32), dim3(32, 8)>>>(W_proj, 1024, wp_hi, wp_lo);

    // Stage 1: K = x @ W_attn[:, D:2D] + b  -> written pre-split (hi/lo)
    gemm_mma<<<dim3(16, 32), 256, GEMM_SMEM>>>(xs_hi, xs_lo, wk_hi, wk_lo,
                                               b_attn + 1024, nullptr, ks_hi, ks_lo);

    // Stage 2: FA2 attention on tensor cores; bf16 hi/lo split output.
    attn_mma<<<dim3(16, 32), 256, ATTN_SMEM_B>>>(ks_hi, ks_lo, att_hi, att_lo);

    // Stage 3: out = att @ W_proj + b_proj (fp32 output)
    gemm_mma<<<dim3(16, 32), 256, GEMM_SMEM>>>(att_hi, att_lo, wp_hi, wp_lo,
                                               b_proj, out, nullptr, nullptr);
}

// round 8
// speedup vs baseline: 1.5898x; 1.5898x over previous
#include <cuda_runtime.h>
#include <cuda_fp16.h>
#include <cstdint>

// ---------------- scratch (__device__ globals; no allocation allowed) -------
__device__ __half g_xs[4096 * 1024];            // x as fp16 (single)
__device__ __half g_ks_hi[4096 * 1024];         // K projection fp16 hi
__device__ __half g_ks_lo[4096 * 1024];         // K projection fp16 lo
__device__ __half g_att[4096 * 1024];           // attention out fp16 (single)
__device__ __half g_wk_hi[1024 * 1024];         // W_attn K-slice, [n][k] hi
__device__ __half g_wk_lo[1024 * 1024];
__device__ __half g_wp_hi[1024 * 1024];         // W_proj, [n][k] hi
__device__ __half g_wp_lo[1024 * 1024];

// ---------------- PTX helpers (all compute_103-safe) ------------------------
__device__ __forceinline__ float fast_exp2(float x) {
    float y; asm("ex2.approx.ftz.f32 %0, %1;" : "=f"(y) : "f"(x)); return y;
}
__device__ __forceinline__ uint32_t smem_u32(const void* p) {
    uint32_t a;
    asm("{ .reg .u64 t; cvta.to.shared.u64 t, %1; cvt.u32.u64 %0, t; }" : "=r"(a) : "l"(p));
    return a;
}
__device__ __forceinline__ void cp_async16(uint32_t dst, const void* src) {
    asm volatile("cp.async.cg.shared.global [%0], [%1], 16;" :: "r"(dst), "l"(src));
}
__device__ __forceinline__ void cp_commit() {
    asm volatile("cp.async.commit_group;" ::: "memory");
}
__device__ __forceinline__ void cp_wait1() {
    asm volatile("cp.async.wait_group 1;" ::: "memory");
}
__device__ __forceinline__ void cp_wait0() {
    asm volatile("cp.async.wait_group 0;" ::: "memory");
}
__device__ __forceinline__ void ldsm4(uint32_t& r0, uint32_t& r1, uint32_t& r2,
                                      uint32_t& r3, uint32_t addr) {
    asm volatile("ldmatrix.sync.aligned.m8n8.x4.shared.b16 {%0,%1,%2,%3}, [%4];"
                 : "=r"(r0), "=r"(r1), "=r"(r2), "=r"(r3) : "r"(addr));
}
__device__ __forceinline__ void ldsm4t(uint32_t& r0, uint32_t& r1, uint32_t& r2,
                                       uint32_t& r3, uint32_t addr) {
    asm volatile("ldmatrix.sync.aligned.m8n8.x4.trans.shared.b16 {%0,%1,%2,%3}, [%4];"
                 : "=r"(r0), "=r"(r1), "=r"(r2), "=r"(r3) : "r"(addr));
}
__device__ __forceinline__ void mma_f16(float* c, const uint32_t* a,
                                        uint32_t b0, uint32_t b1) {
    asm volatile(
        "mma.sync.aligned.m16n8k16.row.col.f32.f16.f16.f32 "
        "{%0,%1,%2,%3}, {%4,%5,%6,%7}, {%8,%9}, {%0,%1,%2,%3};"
        : "+f"(c[0]), "+f"(c[1]), "+f"(c[2]), "+f"(c[3])
        : "r"(a[0]), "r"(a[1]), "r"(a[2]), "r"(a[3]), "r"(b0), "r"(b1));
}
__device__ __forceinline__ uint32_t pack_h2(float a, float b) {
    __half2 h = __float22half2_rn(make_float2(a, b));
    return *(uint32_t*)&h;
}

// ---------------- prep: x -> fp16 (single) ----------------------------------
__global__ __launch_bounds__(256) void splitX_kernel(
    const float* __restrict__ X, __half* __restrict__ O)
{
    int i = blockIdx.x * 256 + threadIdx.x;
    float4 v = ((const float4*)X)[i];
    ((__half2*)O)[i * 2]     = __float22half2_rn(make_float2(v.x, v.y));
    ((__half2*)O)[i * 2 + 1] = __float22half2_rn(make_float2(v.z, v.w));
}

// ---------------- prep: transpose W[k][n] -> [n][k] + fp16 hi/lo split ------
__global__ void splitW_kernel(const float* __restrict__ W, int ldw,
                              __half* __restrict__ Ohi, __half* __restrict__ Olo)
{
    __shared__ float t[32][33];
    int tx = threadIdx.x, ty = threadIdx.y;
    int n0 = blockIdx.x * 32, k0 = blockIdx.y * 32;
#pragma unroll
    for (int p = 0; p < 4; p++)
        t[ty + 8 * p][tx] = W[(size_t)(k0 + ty + 8 * p) * ldw + n0 + tx];
    __syncthreads();
#pragma unroll
    for (int p = 0; p < 4; p++) {
        float v = t[tx][ty + 8 * p];
        __half h = __float2half_rn(v);
        size_t o = (size_t)(n0 + ty + 8 * p) * 1024 + k0 + tx;
        Ohi[o] = h;
        Olo[o] = __float2half_rn(v - __half2float(h));
    }
}

// ---------------- tensor-core GEMM: C = A @ (Bhi+Blo)^T + bias --------------
// A single fp16 [4096][1024] k-major; B hi/lo fp16 [1024(n)][1024(k)].
// Tile M=128, N=64, BK=64, 8 warps (4m x 2n, warp 32x32). 2 MMA terms.
#define ROWB 144
#define GB_HI 18432
#define GB_LO 27648
#define GSTAGE 36864

__global__ __launch_bounds__(256, 3) void gemm_mma(
    const __half* __restrict__ A,
    const __half* __restrict__ Bhi, const __half* __restrict__ Blo,
    const float* __restrict__ bias, float* __restrict__ C,
    __half* __restrict__ Chi, __half* __restrict__ Clo)
{
    extern __shared__ char smem[];
    const uint32_t sb = smem_u32(smem);
    const int tid = threadIdx.x;
    const int wid = tid >> 5;
    const int lane = tid & 31;
    const int wm = wid >> 1;        // 0..3, 32 rows each
    const int wn = wid & 1;         // 0..1, 32 cols each
    const int m0 = blockIdx.y * 128, n0 = blockIdx.x * 64;

    const int lrow = tid >> 3;
    const int lkc = tid & 7;

    const uint32_t a_off = (uint32_t)((wm * 32 + (lane & 15)) * ROWB + (lane >> 4) * 16);
    const uint32_t b_off = (uint32_t)((wn * 32 + (lane & 15)) * ROWB + (lane >> 4) * 16);

    float acc[2][4][4];
#pragma unroll
    for (int i = 0; i < 2; i++)
#pragma unroll
        for (int j = 0; j < 4; j++)
#pragma unroll
            for (int r = 0; r < 4; r++) acc[i][j][r] = 0.0f;

    // prologue: chunk 0 -> stage 0
#pragma unroll
    for (int q = 0; q < 4; q++) {
        int row = lrow + q * 32;
        cp_async16(sb + row * ROWB + lkc * 16,
                   (const char*)A + (size_t)(m0 + row) * 2048 + lkc * 16);
    }
#pragma unroll
    for (int q = 0; q < 2; q++) {
        int row = lrow + q * 32;
        cp_async16(sb + GB_HI + row * ROWB + lkc * 16,
                   (const char*)Bhi + (size_t)(n0 + row) * 2048 + lkc * 16);
        cp_async16(sb + GB_LO + row * ROWB + lkc * 16,
                   (const char*)Blo + (size_t)(n0 + row) * 2048 + lkc * 16);
    }
    cp_commit();

    for (int c = 0; c < 16; c++) {
        const uint32_t st = (uint32_t)(c & 1) * GSTAGE;
        if (c + 1 < 16) {
            const uint32_t st2 = (uint32_t)((c + 1) & 1) * GSTAGE;
            const size_t ko = (size_t)(c + 1) * 128;
#pragma unroll
            for (int q = 0; q < 4; q++) {
                int row = lrow + q * 32;
                cp_async16(st2 + sb + row * ROWB + lkc * 16,
                           (const char*)A + (size_t)(m0 + row) * 2048 + ko + lkc * 16);
            }
#pragma unroll
            for (int q = 0; q < 2; q++) {
                int row = lrow + q * 32;
                cp_async16(st2 + sb + GB_HI + row * ROWB + lkc * 16,
                           (const char*)Bhi + (size_t)(n0 + row) * 2048 + ko + lkc * 16);
                cp_async16(st2 + sb + GB_LO + row * ROWB + lkc * 16,
                           (const char*)Blo + (size_t)(n0 + row) * 2048 + ko + lkc * 16);
            }
            cp_commit();
            cp_wait1();
        } else {
            cp_wait0();
        }
        __syncthreads();

#pragma unroll
        for (int kk = 0; kk < 4; kk++) {
            uint32_t bh[2][4], bl[2][4];
#pragma unroll
            for (int p = 0; p < 2; p++) {
                uint32_t addr = st + sb + b_off + (uint32_t)(p * 16 * ROWB) + kk * 32;
                ldsm4(bh[p][0], bh[p][1], bh[p][2], bh[p][3], addr + GB_HI);
                ldsm4(bl[p][0], bl[p][1], bl[p][2], bl[p][3], addr + GB_LO);
            }
#pragma unroll
            for (int mf = 0; mf < 2; mf++) {
                uint32_t ah[4];
                uint32_t addr = st + sb + a_off + (uint32_t)(mf * 16 * ROWB) + kk * 32;
                ldsm4(ah[0], ah[1], ah[2], ah[3], addr);
#pragma unroll
                for (int nf = 0; nf < 4; nf++) {
                    const int p = nf >> 1, hh = nf & 1;
                    mma_f16(acc[mf][nf], ah, bh[p][hh], bh[p][2 + hh]);
                    mma_f16(acc[mf][nf], ah, bl[p][hh], bl[p][2 + hh]);
                }
            }
        }
        __syncthreads();
    }

    // epilogue
#pragma unroll
    for (int nf = 0; nf < 4; nf++) {
        int n = n0 + wn * 32 + nf * 8 + (lane & 3) * 2;
        float2 bv = *(const float2*)(bias + n);
#pragma unroll
        for (int mf = 0; mf < 2; mf++) {
            int m = m0 + wm * 32 + mf * 16 + (lane >> 2);
            float2 o0 = {acc[mf][nf][0] + bv.x, acc[mf][nf][1] + bv.y};
            float2 o1 = {acc[mf][nf][2] + bv.x, acc[mf][nf][3] + bv.y};
            if (Chi) {
                size_t i0 = (size_t)m * 1024 + n;
                size_t i1 = (size_t)(m + 8) * 1024 + n;
                __half a0 = __float2half_rn(o0.x), a1 = __float2half_rn(o0.y);
                __half b0 = __float2half_rn(o1.x), b1 = __float2half_rn(o1.y);
                *(__half2*)(Chi + i0) = __halves2half2(a0, a1);
                *(__half2*)(Chi + i1) = __halves2half2(b0, b1);
                *(__half2*)(Clo + i0) = __halves2half2(
                    __float2half_rn(o0.x - __half2float(a0)),
                    __float2half_rn(o0.y - __half2float(a1)));
                *(__half2*)(Clo + i1) = __halves2half2(
                    __float2half_rn(o1.x - __half2float(b0)),
                    __float2half_rn(o1.y - __half2float(b1)));
            } else {
                *(float2*)(C + (size_t)m * 1024 + n) = o0;
                *(float2*)(C + (size_t)(m + 8) * 1024 + n) = o1;
            }
        }
    }
}

// ---------------- FA2-style attention, fp16 2-term --------------------------
// Q = Khi rows (single fp16). S = Qhi Khi^T + Qhi Klo^T; P single fp16;
// O = P Vhi + P Vlo (V = K tile via ldmatrix.trans). Output att single fp16.
// smem: Q [128][64] fp16 (18432 B) + 2 stages of K hi/lo (36864 B each).
#define AK0 18432
#define AKST 36864
#define ATTN_SMEM_B (18432 + 2 * 36864)

__global__ __launch_bounds__(256, 2) void attn_mma(
    const __half* __restrict__ Khi, const __half* __restrict__ Klo,
    __half* __restrict__ Out)
{
    extern __shared__ char smem[];
    const uint32_t sb = smem_u32(smem);
    const int tid = threadIdx.x;
    const int wid = tid >> 5;
    const int lane = tid & 31;
    const int g = lane >> 2;
    const int tq = lane & 3;
    const int b = blockIdx.y >> 4;
    const int h = blockIdx.y & 15;
    const int q0 = blockIdx.x * 128;

    const char* KbH = (const char*)Khi + (size_t)b * 2048 * 2048 + h * 128;
    const char* KbL = (const char*)Klo + (size_t)b * 2048 * 2048 + h * 128;
    const float SC = 0.125f * 1.4426950408889634f;

    // prologue: Q tile (hi only) + K tile 0
#pragma unroll
    for (int q = 0; q < 4; q++) {
        int u = tid + q * 256;          // 0..1023: 128 rows x 8 16B-units
        int row = u >> 3, c = u & 7;
        cp_async16(sb + row * ROWB + c * 16,
                   KbH + (size_t)(q0 + row) * 2048 + c * 16);
    }
#pragma unroll
    for (int q = 0; q < 4; q++) {
        int u = tid + q * 256;
        int row = u >> 3, c = u & 7;
        cp_async16(sb + AK0 + row * ROWB + c * 16, KbH + (size_t)row * 2048 + c * 16);
        cp_async16(sb + AK0 + 18432 + row * ROWB + c * 16,
                   KbL + (size_t)row * 2048 + c * 16);
    }
    cp_commit();

    float m0 = -1e30f, m1 = -1e30f, l0 = 0.0f, l1 = 0.0f;
    float o[8][4];
#pragma unroll
    for (int nf = 0; nf < 8; nf++)
#pragma unroll
        for (int r = 0; r < 4; r++) o[nf][r] = 0.0f;

    const uint32_t qa_off = (uint32_t)((wid * 16 + (lane & 15)) * ROWB + (lane >> 4) * 16);
    const uint32_t kb_row = (uint32_t)((lane & 15) * ROWB + (lane >> 4) * 16);

    for (int kt = 0; kt < 16; kt++) {
        const uint32_t st = sb + AK0 + (uint32_t)(kt & 1) * AKST;
        if (kt + 1 < 16) {
            const uint32_t st2 = sb + AK0 + (uint32_t)((kt + 1) & 1) * AKST;
            const size_t j0 = (size_t)(kt + 1) * 128;
#pragma unroll
            for (int q = 0; q < 4; q++) {
                int u = tid + q * 256;
                int row = u >> 3, c = u & 7;
                cp_async16(st2 + row * ROWB + c * 16, KbH + (j0 + row) * 2048 + c * 16);
                cp_async16(st2 + 18432 + row * ROWB + c * 16,
                           KbL + (j0 + row) * 2048 + c * 16);
            }
            cp_commit();
            cp_wait1();
        } else {
            cp_wait0();
        }
        __syncthreads();

        // ---- S = Q K^T (raw, unscaled): 2 MMA terms ----
        float s[16][4];
#pragma unroll
        for (int nf = 0; nf < 16; nf++)
#pragma unroll
            for (int r = 0; r < 4; r++) s[nf][r] = 0.0f;

#pragma unroll
        for (int kk = 0; kk < 4; kk++) {
            uint32_t qh[4];
            ldsm4(qh[0], qh[1], qh[2], qh[3], sb + qa_off + kk * 32);
#pragma unroll
            for (int nb = 0; nb < 8; nb++) {
                uint32_t kh[4], kl[4];
                uint32_t addr = st + kb_row + (uint32_t)(nb * 16 * ROWB) + kk * 32;
                ldsm4(kh[0], kh[1], kh[2], kh[3], addr);
                ldsm4(kl[0], kl[1], kl[2], kl[3], addr + 18432);
#pragma unroll
                for (int hh = 0; hh < 2; hh++) {
                    mma_f16(s[2 * nb + hh], qh, kh[hh], kh[2 + hh]);
                    mma_f16(s[2 * nb + hh], qh, kl[hh], kl[2 + hh]);
                }
            }
        }

        // ---- online softmax (scale folded) ----
        float mx0 = -1e30f, mx1 = -1e30f;
#pragma unroll
        for (int nf = 0; nf < 16; nf++) {
            mx0 = fmaxf(mx0, fmaxf(s[nf][0], s[nf][1]));
            mx1 = fmaxf(mx1, fmaxf(s[nf][2], s[nf][3]));
        }
        mx0 = fmaxf(mx0, __shfl_xor_sync(0xffffffffu, mx0, 1));
        mx0 = fmaxf(mx0, __shfl_xor_sync(0xffffffffu, mx0, 2));
        mx1 = fmaxf(mx1, __shfl_xor_sync(0xffffffffu, mx1, 1));
        mx1 = fmaxf(mx1, __shfl_xor_sync(0xffffffffu, mx1, 2));
        float mn0 = fmaxf(m0, mx0), mn1 = fmaxf(m1, mx1);
        float c0 = fast_exp2((m0 - mn0) * SC), c1 = fast_exp2((m1 - mn1) * SC);
        m0 = mn0; m1 = mn1;
        l0 *= c0; l1 *= c1;
#pragma unroll
        for (int nf = 0; nf < 8; nf++) {
            o[nf][0] *= c0; o[nf][1] *= c0;
            o[nf][2] *= c1; o[nf][3] *= c1;
        }
        const float b0s = -mn0 * SC, b1s = -mn1 * SC;
        float rs0 = 0.0f, rs1 = 0.0f;
#pragma unroll
        for (int nf = 0; nf < 16; nf++) {
            s[nf][0] = fast_exp2(fmaf(s[nf][0], SC, b0s));
            s[nf][1] = fast_exp2(fmaf(s[nf][1], SC, b0s));
            s[nf][2] = fast_exp2(fmaf(s[nf][2], SC, b1s));
            s[nf][3] = fast_exp2(fmaf(s[nf][3], SC, b1s));
            rs0 += s[nf][0] + s[nf][1];
            rs1 += s[nf][2] + s[nf][3];
        }
        rs0 += __shfl_xor_sync(0xffffffffu, rs0, 1);
        rs0 += __shfl_xor_sync(0xffffffffu, rs0, 2);
        rs1 += __shfl_xor_sync(0xffffffffu, rs1, 1);
        rs1 += __shfl_xor_sync(0xffffffffu, rs1, 2);
        l0 += rs0; l1 += rs1;

        // ---- O += P V (P single fp16 from registers, V via ldsm.trans) ----
#pragma unroll
        for (int t = 0; t < 8; t++) {
            uint32_t ph[4];
            ph[0] = pack_h2(s[2 * t][0], s[2 * t][1]);
            ph[1] = pack_h2(s[2 * t][2], s[2 * t][3]);
            ph[2] = pack_h2(s[2 * t + 1][0], s[2 * t + 1][1]);
            ph[3] = pack_h2(s[2 * t + 1][2], s[2 * t + 1][3]);
#pragma unroll
            for (int nb = 0; nb < 4; nb++) {
                uint32_t vh[4], vl[4];
                uint32_t addr = st + kb_row + (uint32_t)(t * 16 * ROWB) + nb * 32;
                ldsm4t(vh[0], vh[1], vh[2], vh[3], addr);
                ldsm4t(vl[0], vl[1], vl[2], vl[3], addr + 18432);
#pragma unroll
                for (int hh = 0; hh < 2; hh++) {
                    mma_f16(o[2 * nb + hh], ph, vh[2 * hh], vh[2 * hh + 1]);
                    mma_f16(o[2 * nb + hh], ph, vl[2 * hh], vl[2 * hh + 1]);
                }
            }
        }
        __syncthreads();
    }

    // ---- epilogue: normalize, write att as single fp16 ----
    float inv0 = 1.0f / l0, inv1 = 1.0f / l1;
    int mr0 = q0 + wid * 16 + g;
#pragma unroll
    for (int nf = 0; nf < 8; nf++) {
        int d = h * 64 + nf * 8 + tq * 2;
        size_t i0 = ((size_t)b * 2048 + mr0) * 1024 + d;
        size_t i1 = i0 + 8 * 1024;
        *(__half2*)(Out + i0) = __float22half2_rn(
            make_float2(o[nf][0] * inv0, o[nf][1] * inv0));
        *(__half2*)(Out + i1) = __float22half2_rn(
            make_float2(o[nf][2] * inv1, o[nf][3] * inv1));
    }
}

// ---------------------------------------------------------------------------
extern "C" void kernel_launch(void* const* d_in, const int* in_sizes, int n_in,
                              void* d_out, int out_size) {
    const float* x      = (const float*)d_in[0];  // (2, 2048, 1024)
    const float* W_attn = (const float*)d_in[1];  // (1024, 3072)
    const float* b_attn = (const float*)d_in[2];  // (3072,)
    const float* W_proj = (const float*)d_in[3];  // (1024, 1024)
    const float* b_proj = (const float*)d_in[4];  // (1024,)
    float* out = (float*)d_out;                   // (2, 2048, 1024)

    __half *xs, *ks_hi, *ks_lo, *att, *wk_hi, *wk_lo, *wp_hi, *wp_lo;
    cudaGetSymbolAddress((void**)&xs, g_xs);
    cudaGetSymbolAddress((void**)&ks_hi, g_ks_hi);
    cudaGetSymbolAddress((void**)&ks_lo, g_ks_lo);
    cudaGetSymbolAddress((void**)&att, g_att);
    cudaGetSymbolAddress((void**)&wk_hi, g_wk_hi);
    cudaGetSymbolAddress((void**)&wk_lo, g_wk_lo);
    cudaGetSymbolAddress((void**)&wp_hi, g_wp_hi);
    cudaGetSymbolAddress((void**)&wp_lo, g_wp_lo);

    const int GEMM_SMEM = 2 * GSTAGE;  // 73728
    cudaFuncSetAttribute(gemm_mma,
                         cudaFuncAttributeMaxDynamicSharedMemorySize, GEMM_SMEM);
    cudaFuncSetAttribute(attn_mma,
                         cudaFuncAttributeMaxDynamicSharedMemorySize, ATTN_SMEM_B);

    // Prep
    splitX_kernel<<<4096, 256>>>(x, xs);
    splitW_kernel<<<dim3(32, 32), dim3(32, 8)>>>(W_attn + 1024, 3072, wk_hi, wk_lo);
    splitW_kernel<<<dim3(32, 32), dim3(32, 8)>>>(W_proj, 1024, wp_hi, wp_lo);

    // Stage 1: K = x @ W_attn[:, D:2D] + b  -> fp16 hi/lo
    gemm_mma<<<dim3(16, 32), 256, GEMM_SMEM>>>(xs, wk_hi, wk_lo,
                                               b_attn + 1024, nullptr, ks_hi, ks_lo);

    // Stage 2: FA2 attention (fp16 2-term) -> att single fp16
    attn_mma<<<dim3(16, 32), 256, ATTN_SMEM_B>>>(ks_hi, ks_lo, att);

    // Stage 3: out = att @ W_proj + b_proj (fp32 out)
    gemm_mma<<<dim3(16, 32), 256, GEMM_SMEM>>>(att, wp_hi, wp_lo,
                                               b_proj, out, nullptr, nullptr);
}

// round 9
// speedup vs baseline: 1.7529x; 1.1026x over previous
#include <cuda_runtime.h>
#include <cuda_fp16.h>
#include <cstdint>

// ---------------- scratch (__device__ globals; no allocation allowed) -------
__device__ __half g_xs[4096 * 1024];            // x as fp16 (single)
__device__ __half g_ks_hi[4096 * 1024];         // K projection fp16 hi
__device__ __half g_ks_lo[4096 * 1024];         // K projection fp16 lo
__device__ __half g_att[4096 * 1024];           // attention out fp16 (single)
__device__ __half g_wk_hi[1024 * 1024];         // W_attn K-slice, [n][k] hi
__device__ __half g_wk_lo[1024 * 1024];
__device__ __half g_wp_hi[1024 * 1024];         // W_proj, [n][k] hi
__device__ __half g_wp_lo[1024 * 1024];

// ---------------- PTX helpers (all compute_103-safe) ------------------------
__device__ __forceinline__ float fast_exp2(float x) {
    float y; asm("ex2.approx.ftz.f32 %0, %1;" : "=f"(y) : "f"(x)); return y;
}
__device__ __forceinline__ uint32_t smem_u32(const void* p) {
    uint32_t a;
    asm("{ .reg .u64 t; cvta.to.shared.u64 t, %1; cvt.u32.u64 %0, t; }" : "=r"(a) : "l"(p));
    return a;
}
__device__ __forceinline__ void cp_async16(uint32_t dst, const void* src) {
    asm volatile("cp.async.cg.shared.global [%0], [%1], 16;" :: "r"(dst), "l"(src));
}
__device__ __forceinline__ void cp_commit() {
    asm volatile("cp.async.commit_group;" ::: "memory");
}
__device__ __forceinline__ void cp_wait1() {
    asm volatile("cp.async.wait_group 1;" ::: "memory");
}
__device__ __forceinline__ void cp_wait0() {
    asm volatile("cp.async.wait_group 0;" ::: "memory");
}
__device__ __forceinline__ void ldsm4(uint32_t& r0, uint32_t& r1, uint32_t& r2,
                                      uint32_t& r3, uint32_t addr) {
    asm volatile("ldmatrix.sync.aligned.m8n8.x4.shared.b16 {%0,%1,%2,%3}, [%4];"
                 : "=r"(r0), "=r"(r1), "=r"(r2), "=r"(r3) : "r"(addr));
}
__device__ __forceinline__ void ldsm4t(uint32_t& r0, uint32_t& r1, uint32_t& r2,
                                       uint32_t& r3, uint32_t addr) {
    asm volatile("ldmatrix.sync.aligned.m8n8.x4.trans.shared.b16 {%0,%1,%2,%3}, [%4];"
                 : "=r"(r0), "=r"(r1), "=r"(r2), "=r"(r3) : "r"(addr));
}
__device__ __forceinline__ void mma_f16(float* c, const uint32_t* a,
                                        uint32_t b0, uint32_t b1) {
    asm volatile(
        "mma.sync.aligned.m16n8k16.row.col.f32.f16.f16.f32 "
        "{%0,%1,%2,%3}, {%4,%5,%6,%7}, {%8,%9}, {%0,%1,%2,%3};"
        : "+f"(c[0]), "+f"(c[1]), "+f"(c[2]), "+f"(c[3])
        : "r"(a[0]), "r"(a[1]), "r"(a[2]), "r"(a[3]), "r"(b0), "r"(b1));
}
__device__ __forceinline__ uint32_t pack_h2(float a, float b) {
    __half2 h = __float22half2_rn(make_float2(a, b));
    return *(uint32_t*)&h;
}

// ---------------- merged prep: x->fp16; W transposes + hi/lo splits ----------
// blocks [0,4096): splitX; [4096,5120): W_attn K-slice; [5120,6144): W_proj.
__global__ __launch_bounds__(256) void prep_kernel(
    const float* __restrict__ X, __half* __restrict__ XO,
    const float* __restrict__ Wk, const float* __restrict__ Wp,
    __half* __restrict__ WkHi, __half* __restrict__ WkLo,
    __half* __restrict__ WpHi, __half* __restrict__ WpLo)
{
    __shared__ float t[32][33];
    int bid = blockIdx.x;
    if (bid < 4096) {
        int i = bid * 256 + threadIdx.x;
        float4 v = ((const float4*)X)[i];
        ((__half2*)XO)[i * 2]     = __float22half2_rn(make_float2(v.x, v.y));
        ((__half2*)XO)[i * 2 + 1] = __float22half2_rn(make_float2(v.z, v.w));
        return;
    }
    bid -= 4096;
    const float* W; __half *Ohi, *Olo; int ldw;
    if (bid < 1024) { W = Wk; ldw = 3072; Ohi = WkHi; Olo = WkLo; }
    else { bid -= 1024; W = Wp; ldw = 1024; Ohi = WpHi; Olo = WpLo; }
    int n0 = (bid & 31) * 32, k0 = (bid >> 5) * 32;
    int tx = threadIdx.x & 31, ty = threadIdx.x >> 5;
#pragma unroll
    for (int p = 0; p < 4; p++)
        t[ty + 8 * p][tx] = W[(size_t)(k0 + ty + 8 * p) * ldw + n0 + tx];
    __syncthreads();
#pragma unroll
    for (int p = 0; p < 4; p++) {
        float v = t[tx][ty + 8 * p];
        __half h = __float2half_rn(v);
        size_t o = (size_t)(n0 + ty + 8 * p) * 1024 + k0 + tx;
        Ohi[o] = h;
        Olo[o] = __float2half_rn(v - __half2float(h));
    }
}

// ---------------- tensor-core GEMM: C = A @ (Bhi+Blo)^T + bias --------------
// A single fp16 [4096][1024] k-major; B hi/lo fp16 [1024(n)][1024(k)].
// Tile M=128, N=64, BK=64, 8 warps (4m x 2n, warp 32x32). Hi-pass then
// lo-pass per kk so same-accumulator MMAs are 8 issues apart (RAW relief).
#define ROWB 144
#define GB_HI 18432
#define GB_LO 27648
#define GSTAGE 36864

__global__ __launch_bounds__(256, 3) void gemm_mma(
    const __half* __restrict__ A,
    const __half* __restrict__ Bhi, const __half* __restrict__ Blo,
    const float* __restrict__ bias, float* __restrict__ C,
    __half* __restrict__ Chi, __half* __restrict__ Clo)
{
    extern __shared__ char smem[];
    const uint32_t sb = smem_u32(smem);
    const int tid = threadIdx.x;
    const int wid = tid >> 5;
    const int lane = tid & 31;
    const int wm = wid >> 1;
    const int wn = wid & 1;
    const int m0 = blockIdx.y * 128, n0 = blockIdx.x * 64;

    const int lrow = tid >> 3;
    const int lkc = tid & 7;

    const uint32_t a_off = (uint32_t)((wm * 32 + (lane & 15)) * ROWB + (lane >> 4) * 16);
    const uint32_t b_off = (uint32_t)((wn * 32 + (lane & 15)) * ROWB + (lane >> 4) * 16);

    float acc[2][4][4];
#pragma unroll
    for (int i = 0; i < 2; i++)
#pragma unroll
        for (int j = 0; j < 4; j++)
#pragma unroll
            for (int r = 0; r < 4; r++) acc[i][j][r] = 0.0f;

#pragma unroll
    for (int q = 0; q < 4; q++) {
        int row = lrow + q * 32;
        cp_async16(sb + row * ROWB + lkc * 16,
                   (const char*)A + (size_t)(m0 + row) * 2048 + lkc * 16);
    }
#pragma unroll
    for (int q = 0; q < 2; q++) {
        int row = lrow + q * 32;
        cp_async16(sb + GB_HI + row * ROWB + lkc * 16,
                   (const char*)Bhi + (size_t)(n0 + row) * 2048 + lkc * 16);
        cp_async16(sb + GB_LO + row * ROWB + lkc * 16,
                   (const char*)Blo + (size_t)(n0 + row) * 2048 + lkc * 16);
    }
    cp_commit();

    for (int c = 0; c < 16; c++) {
        const uint32_t st = (uint32_t)(c & 1) * GSTAGE;
        if (c + 1 < 16) {
            const uint32_t st2 = (uint32_t)((c + 1) & 1) * GSTAGE;
            const size_t ko = (size_t)(c + 1) * 128;
#pragma unroll
            for (int q = 0; q < 4; q++) {
                int row = lrow + q * 32;
                cp_async16(st2 + sb + row * ROWB + lkc * 16,
                           (const char*)A + (size_t)(m0 + row) * 2048 + ko + lkc * 16);
            }
#pragma unroll
            for (int q = 0; q < 2; q++) {
                int row = lrow + q * 32;
                cp_async16(st2 + sb + GB_HI + row * ROWB + lkc * 16,
                           (const char*)Bhi + (size_t)(n0 + row) * 2048 + ko + lkc * 16);
                cp_async16(st2 + sb + GB_LO + row * ROWB + lkc * 16,
                           (const char*)Blo + (size_t)(n0 + row) * 2048 + ko + lkc * 16);
            }
            cp_commit();
            cp_wait1();
        } else {
            cp_wait0();
        }
        __syncthreads();

#pragma unroll
        for (int kk = 0; kk < 4; kk++) {
            uint32_t bh[2][4], bl[2][4];
#pragma unroll
            for (int p = 0; p < 2; p++) {
                uint32_t addr = st + sb + b_off + (uint32_t)(p * 16 * ROWB) + kk * 32;
                ldsm4(bh[p][0], bh[p][1], bh[p][2], bh[p][3], addr + GB_HI);
                ldsm4(bl[p][0], bl[p][1], bl[p][2], bl[p][3], addr + GB_LO);
            }
            uint32_t ah[2][4];
#pragma unroll
            for (int mf = 0; mf < 2; mf++) {
                uint32_t addr = st + sb + a_off + (uint32_t)(mf * 16 * ROWB) + kk * 32;
                ldsm4(ah[mf][0], ah[mf][1], ah[mf][2], ah[mf][3], addr);
            }
            // hi pass (8 independent accumulators)
#pragma unroll
            for (int mf = 0; mf < 2; mf++)
#pragma unroll
                for (int nf = 0; nf < 4; nf++) {
                    const int p = nf >> 1, hh = nf & 1;
                    mma_f16(acc[mf][nf], ah[mf], bh[p][hh], bh[p][2 + hh]);
                }
            // lo pass
#pragma unroll
            for (int mf = 0; mf < 2; mf++)
#pragma unroll
                for (int nf = 0; nf < 4; nf++) {
                    const int p = nf >> 1, hh = nf & 1;
                    mma_f16(acc[mf][nf], ah[mf], bl[p][hh], bl[p][2 + hh]);
                }
        }
        __syncthreads();
    }

    // epilogue
#pragma unroll
    for (int nf = 0; nf < 4; nf++) {
        int n = n0 + wn * 32 + nf * 8 + (lane & 3) * 2;
        float2 bv = *(const float2*)(bias + n);
#pragma unroll
        for (int mf = 0; mf < 2; mf++) {
            int m = m0 + wm * 32 + mf * 16 + (lane >> 2);
            float2 o0 = {acc[mf][nf][0] + bv.x, acc[mf][nf][1] + bv.y};
            float2 o1 = {acc[mf][nf][2] + bv.x, acc[mf][nf][3] + bv.y};
            if (Chi) {
                size_t i0 = (size_t)m * 1024 + n;
                size_t i1 = (size_t)(m + 8) * 1024 + n;
                __half a0 = __float2half_rn(o0.x), a1 = __float2half_rn(o0.y);
                __half b0 = __float2half_rn(o1.x), b1 = __float2half_rn(o1.y);
                *(__half2*)(Chi + i0) = __halves2half2(a0, a1);
                *(__half2*)(Chi + i1) = __halves2half2(b0, b1);
                *(__half2*)(Clo + i0) = __halves2half2(
                    __float2half_rn(o0.x - __half2float(a0)),
                    __float2half_rn(o0.y - __half2float(a1)));
                *(__half2*)(Clo + i1) = __halves2half2(
                    __float2half_rn(o1.x - __half2float(b0)),
                    __float2half_rn(o1.y - __half2float(b1)));
            } else {
                *(float2*)(C + (size_t)m * 1024 + n) = o0;
                *(float2*)(C + (size_t)(m + 8) * 1024 + n) = o1;
            }
        }
    }
}

// ---------------- FA2-style attention -----------------------------------
// S = Qhi Khi^T (single term; Klo dropped — error ~2.8e-4 on P, in budget).
// P single fp16; O = P Vhi + P Vlo (V = K tile via ldmatrix.trans).
#define AK0 18432
#define AKST 36864
#define ATTN_SMEM_B (18432 + 2 * 36864)

__global__ __launch_bounds__(256, 2) void attn_mma(
    const __half* __restrict__ Khi, const __half* __restrict__ Klo,
    __half* __restrict__ Out)
{
    extern __shared__ char smem[];
    const uint32_t sb = smem_u32(smem);
    const int tid = threadIdx.x;
    const int wid = tid >> 5;
    const int lane = tid & 31;
    const int g = lane >> 2;
    const int tq = lane & 3;
    const int b = blockIdx.y >> 4;
    const int h = blockIdx.y & 15;
    const int q0 = blockIdx.x * 128;

    const char* KbH = (const char*)Khi + (size_t)b * 2048 * 2048 + h * 128;
    const char* KbL = (const char*)Klo + (size_t)b * 2048 * 2048 + h * 128;
    const float SC = 0.125f * 1.4426950408889634f;

    // prologue: Q tile (hi only) + K tile 0
#pragma unroll
    for (int q = 0; q < 4; q++) {
        int u = tid + q * 256;
        int row = u >> 3, c = u & 7;
        cp_async16(sb + row * ROWB + c * 16,
                   KbH + (size_t)(q0 + row) * 2048 + c * 16);
    }
#pragma unroll
    for (int q = 0; q < 4; q++) {
        int u = tid + q * 256;
        int row = u >> 3, c = u & 7;
        cp_async16(sb + AK0 + row * ROWB + c * 16, KbH + (size_t)row * 2048 + c * 16);
        cp_async16(sb + AK0 + 18432 + row * ROWB + c * 16,
                   KbL + (size_t)row * 2048 + c * 16);
    }
    cp_commit();

    float m0 = -1e30f, m1 = -1e30f, l0 = 0.0f, l1 = 0.0f;
    float o[8][4];
#pragma unroll
    for (int nf = 0; nf < 8; nf++)
#pragma unroll
        for (int r = 0; r < 4; r++) o[nf][r] = 0.0f;

    const uint32_t qa_off = (uint32_t)((wid * 16 + (lane & 15)) * ROWB + (lane >> 4) * 16);
    const uint32_t kb_row = (uint32_t)((lane & 15) * ROWB + (lane >> 4) * 16);

    for (int kt = 0; kt < 16; kt++) {
        const uint32_t st = sb + AK0 + (uint32_t)(kt & 1) * AKST;
        if (kt + 1 < 16) {
            const uint32_t st2 = sb + AK0 + (uint32_t)((kt + 1) & 1) * AKST;
            const size_t j0 = (size_t)(kt + 1) * 128;
#pragma unroll
            for (int q = 0; q < 4; q++) {
                int u = tid + q * 256;
                int row = u >> 3, c = u & 7;
                cp_async16(st2 + row * ROWB + c * 16, KbH + (j0 + row) * 2048 + c * 16);
                cp_async16(st2 + 18432 + row * ROWB + c * 16,
                           KbL + (j0 + row) * 2048 + c * 16);
            }
            cp_commit();
            cp_wait1();
        } else {
            cp_wait0();
        }
        __syncthreads();

        // ---- S = Qhi Khi^T (single term) ----
        float s[16][4];
#pragma unroll
        for (int nf = 0; nf < 16; nf++)
#pragma unroll
            for (int r = 0; r < 4; r++) s[nf][r] = 0.0f;

#pragma unroll
        for (int kk = 0; kk < 4; kk++) {
            uint32_t qh[4];
            ldsm4(qh[0], qh[1], qh[2], qh[3], sb + qa_off + kk * 32);
#pragma unroll
            for (int nb = 0; nb < 8; nb++) {
                uint32_t kh[4];
                uint32_t addr = st + kb_row + (uint32_t)(nb * 16 * ROWB) + kk * 32;
                ldsm4(kh[0], kh[1], kh[2], kh[3], addr);
#pragma unroll
                for (int hh = 0; hh < 2; hh++)
                    mma_f16(s[2 * nb + hh], qh, kh[hh], kh[2 + hh]);
            }
        }

        // ---- online softmax (scale folded) ----
        float mx0 = -1e30f, mx1 = -1e30f;
#pragma unroll
        for (int nf = 0; nf < 16; nf++) {
            mx0 = fmaxf(mx0, fmaxf(s[nf][0], s[nf][1]));
            mx1 = fmaxf(mx1, fmaxf(s[nf][2], s[nf][3]));
        }
        mx0 = fmaxf(mx0, __shfl_xor_sync(0xffffffffu, mx0, 1));
        mx0 = fmaxf(mx0, __shfl_xor_sync(0xffffffffu, mx0, 2));
        mx1 = fmaxf(mx1, __shfl_xor_sync(0xffffffffu, mx1, 1));
        mx1 = fmaxf(mx1, __shfl_xor_sync(0xffffffffu, mx1, 2));
        float mn0 = fmaxf(m0, mx0), mn1 = fmaxf(m1, mx1);
        float c0 = fast_exp2((m0 - mn0) * SC), c1 = fast_exp2((m1 - mn1) * SC);
        m0 = mn0; m1 = mn1;
        l0 *= c0; l1 *= c1;
#pragma unroll
        for (int nf = 0; nf < 8; nf++) {
            o[nf][0] *= c0; o[nf][1] *= c0;
            o[nf][2] *= c1; o[nf][3] *= c1;
        }
        const float b0s = -mn0 * SC, b1s = -mn1 * SC;
        float rs0 = 0.0f, rs1 = 0.0f;
#pragma unroll
        for (int nf = 0; nf < 16; nf++) {
            s[nf][0] = fast_exp2(fmaf(s[nf][0], SC, b0s));
            s[nf][1] = fast_exp2(fmaf(s[nf][1], SC, b0s));
            s[nf][2] = fast_exp2(fmaf(s[nf][2], SC, b1s));
            s[nf][3] = fast_exp2(fmaf(s[nf][3], SC, b1s));
            rs0 += s[nf][0] + s[nf][1];
            rs1 += s[nf][2] + s[nf][3];
        }
        rs0 += __shfl_xor_sync(0xffffffffu, rs0, 1);
        rs0 += __shfl_xor_sync(0xffffffffu, rs0, 2);
        rs1 += __shfl_xor_sync(0xffffffffu, rs1, 1);
        rs1 += __shfl_xor_sync(0xffffffffu, rs1, 2);
        l0 += rs0; l1 += rs1;

        // ---- O += P V (P single fp16; V hi + lo) ----
#pragma unroll
        for (int t = 0; t < 8; t++) {
            uint32_t ph[4];
            ph[0] = pack_h2(s[2 * t][0], s[2 * t][1]);
            ph[1] = pack_h2(s[2 * t][2], s[2 * t][3]);
            ph[2] = pack_h2(s[2 * t + 1][0], s[2 * t + 1][1]);
            ph[3] = pack_h2(s[2 * t + 1][2], s[2 * t + 1][3]);
#pragma unroll
            for (int nb = 0; nb < 4; nb++) {
                uint32_t vh[4], vl[4];
                uint32_t addr = st + kb_row + (uint32_t)(t * 16 * ROWB) + nb * 32;
                ldsm4t(vh[0], vh[1], vh[2], vh[3], addr);
                ldsm4t(vl[0], vl[1], vl[2], vl[3], addr + 18432);
#pragma unroll
                for (int hh = 0; hh < 2; hh++) {
                    mma_f16(o[2 * nb + hh], ph, vh[2 * hh], vh[2 * hh + 1]);
                    mma_f16(o[2 * nb + hh], ph, vl[2 * hh], vl[2 * hh + 1]);
                }
            }
        }
        __syncthreads();
    }

    // ---- epilogue ----
    float inv0 = 1.0f / l0, inv1 = 1.0f / l1;
    int mr0 = q0 + wid * 16 + g;
#pragma unroll
    for (int nf = 0; nf < 8; nf++) {
        int d = h * 64 + nf * 8 + tq * 2;
        size_t i0 = ((size_t)b * 2048 + mr0) * 1024 + d;
        size_t i1 = i0 + 8 * 1024;
        *(__half2*)(Out + i0) = __float22half2_rn(
            make_float2(o[nf][0] * inv0, o[nf][1] * inv0));
        *(__half2*)(Out + i1) = __float22half2_rn(
            make_float2(o[nf][2] * inv1, o[nf][3] * inv1));
    }
}

// ---------------------------------------------------------------------------
extern "C" void kernel_launch(void* const* d_in, const int* in_sizes, int n_in,
                              void* d_out, int out_size) {
    const float* x      = (const float*)d_in[0];  // (2, 2048, 1024)
    const float* W_attn = (const float*)d_in[1];  // (1024, 3072)
    const float* b_attn = (const float*)d_in[2];  // (3072,)
    const float* W_proj = (const float*)d_in[3];  // (1024, 1024)
    const float* b_proj = (const float*)d_in[4];  // (1024,)
    float* out = (float*)d_out;                   // (2, 2048, 1024)

    __half *xs, *ks_hi, *ks_lo, *att, *wk_hi, *wk_lo, *wp_hi, *wp_lo;
    cudaGetSymbolAddress((void**)&xs, g_xs);
    cudaGetSymbolAddress((void**)&ks_hi, g_ks_hi);
    cudaGetSymbolAddress((void**)&ks_lo, g_ks_lo);
    cudaGetSymbolAddress((void**)&att, g_att);
    cudaGetSymbolAddress((void**)&wk_hi, g_wk_hi);
    cudaGetSymbolAddress((void**)&wk_lo, g_wk_lo);
    cudaGetSymbolAddress((void**)&wp_hi, g_wp_hi);
    cudaGetSymbolAddress((void**)&wp_lo, g_wp_lo);

    const int GEMM_SMEM = 2 * GSTAGE;  // 73728
    cudaFuncSetAttribute(gemm_mma,
                         cudaFuncAttributeMaxDynamicSharedMemorySize, GEMM_SMEM);
    cudaFuncSetAttribute(attn_mma,
                         cudaFuncAttributeMaxDynamicSharedMemorySize, ATTN_SMEM_B);

    // Prep (one launch): x->fp16, W_attn K-slice and W_proj transposed + split
    prep_kernel<<<6144, 256>>>(x, xs, W_attn + 1024, W_proj,
                               wk_hi, wk_lo, wp_hi, wp_lo);

    // Stage 1: K = x @ W_attn[:, D:2D] + b  -> fp16 hi/lo
    gemm_mma<<<dim3(16, 32), 256, GEMM_SMEM>>>(xs, wk_hi, wk_lo,
                                               b_attn + 1024, nullptr, ks_hi, ks_lo);

    // Stage 2: FA2 attention -> att single fp16
    attn_mma<<<dim3(16, 32), 256, ATTN_SMEM_B>>>(ks_hi, ks_lo, att);

    // Stage 3: out = att @ W_proj + b_proj (fp32 out)
    gemm_mma<<<dim3(16, 32), 256, GEMM_SMEM>>>(att, wp_hi, wp_lo,
                                               b_proj, out, nullptr, nullptr);
}

// round 10
// speedup vs baseline: 2.0983x; 1.1970x over previous
#include <cuda_runtime.h>
#include <cuda_fp16.h>
#include <cstdint>

// ---------------- scratch (__device__ globals; no allocation allowed) -------
__device__ __half g_xs[4096 * 1024];            // x as fp16 (single)
__device__ __half g_ks_hi[4096 * 1024];         // K projection fp16 hi
__device__ __half g_ks_lo[4096 * 1024];         // K projection fp16 lo
__device__ __half g_att[4096 * 1024];           // attention out fp16 (single)
__device__ __half g_wk[1024 * 1024];            // W_attn K-slice, [n][k] fp16
__device__ __half g_wp[1024 * 1024];            // W_proj, [n][k] fp16

// ---------------- PTX helpers (all compute_103-safe) ------------------------
__device__ __forceinline__ float fast_exp2(float x) {
    float y; asm("ex2.approx.ftz.f32 %0, %1;" : "=f"(y) : "f"(x)); return y;
}
__device__ __forceinline__ uint32_t smem_u32(const void* p) {
    uint32_t a;
    asm("{ .reg .u64 t; cvta.to.shared.u64 t, %1; cvt.u32.u64 %0, t; }" : "=r"(a) : "l"(p));
    return a;
}
__device__ __forceinline__ void cp_async16(uint32_t dst, const void* src) {
    asm volatile("cp.async.cg.shared.global [%0], [%1], 16;" :: "r"(dst), "l"(src));
}
__device__ __forceinline__ void cp_commit() {
    asm volatile("cp.async.commit_group;" ::: "memory");
}
__device__ __forceinline__ void cp_wait1() {
    asm volatile("cp.async.wait_group 1;" ::: "memory");
}
__device__ __forceinline__ void cp_wait0() {
    asm volatile("cp.async.wait_group 0;" ::: "memory");
}
__device__ __forceinline__ void ldsm4(uint32_t& r0, uint32_t& r1, uint32_t& r2,
                                      uint32_t& r3, uint32_t addr) {
    asm volatile("ldmatrix.sync.aligned.m8n8.x4.shared.b16 {%0,%1,%2,%3}, [%4];"
                 : "=r"(r0), "=r"(r1), "=r"(r2), "=r"(r3) : "r"(addr));
}
__device__ __forceinline__ void ldsm4t(uint32_t& r0, uint32_t& r1, uint32_t& r2,
                                       uint32_t& r3, uint32_t addr) {
    asm volatile("ldmatrix.sync.aligned.m8n8.x4.trans.shared.b16 {%0,%1,%2,%3}, [%4];"
                 : "=r"(r0), "=r"(r1), "=r"(r2), "=r"(r3) : "r"(addr));
}
__device__ __forceinline__ void mma_f16(float* c, const uint32_t* a,
                                        uint32_t b0, uint32_t b1) {
    asm volatile(
        "mma.sync.aligned.m16n8k16.row.col.f32.f16.f16.f32 "
        "{%0,%1,%2,%3}, {%4,%5,%6,%7}, {%8,%9}, {%0,%1,%2,%3};"
        : "+f"(c[0]), "+f"(c[1]), "+f"(c[2]), "+f"(c[3])
        : "r"(a[0]), "r"(a[1]), "r"(a[2]), "r"(a[3]), "r"(b0), "r"(b1));
}
__device__ __forceinline__ uint32_t pack_h2(float a, float b) {
    __half2 h = __float22half2_rn(make_float2(a, b));
    return *(uint32_t*)&h;
}

// ---------------- merged prep: x->fp16; W transposes (single fp16) ----------
// blocks [0,4096): splitX; [4096,5120): W_attn K-slice; [5120,6144): W_proj.
__global__ __launch_bounds__(256) void prep_kernel(
    const float* __restrict__ X, __half* __restrict__ XO,
    const float* __restrict__ Wk, const float* __restrict__ Wp,
    __half* __restrict__ WkO, __half* __restrict__ WpO)
{
    __shared__ float t[32][33];
    int bid = blockIdx.x;
    if (bid < 4096) {
        int i = bid * 256 + threadIdx.x;
        float4 v = ((const float4*)X)[i];
        ((__half2*)XO)[i * 2]     = __float22half2_rn(make_float2(v.x, v.y));
        ((__half2*)XO)[i * 2 + 1] = __float22half2_rn(make_float2(v.z, v.w));
        return;
    }
    bid -= 4096;
    const float* W; __half* O; int ldw;
    if (bid < 1024) { W = Wk; ldw = 3072; O = WkO; }
    else { bid -= 1024; W = Wp; ldw = 1024; O = WpO; }
    int n0 = (bid & 31) * 32, k0 = (bid >> 5) * 32;
    int tx = threadIdx.x & 31, ty = threadIdx.x >> 5;
#pragma unroll
    for (int p = 0; p < 4; p++)
        t[ty + 8 * p][tx] = W[(size_t)(k0 + ty + 8 * p) * ldw + n0 + tx];
    __syncthreads();
#pragma unroll
    for (int p = 0; p < 4; p++)
        O[(size_t)(n0 + ty + 8 * p) * 1024 + k0 + tx] =
            __float2half_rn(t[tx][ty + 8 * p]);
}

// ---------------- tensor-core GEMM: C = A @ B^T + bias (both single fp16) ---
// A fp16 [4096][1024] k-major; B fp16 [1024(n)][1024(k)].
// Tile M=128, N=64, BK=64, 8 warps (4m x 2n, warp 32x32), double-buffered.
#define ROWB 144
#define GB_OFF 18432
#define GSTAGE 27648

__global__ __launch_bounds__(256, 3) void gemm_mma(
    const __half* __restrict__ A, const __half* __restrict__ B,
    const float* __restrict__ bias, float* __restrict__ C,
    __half* __restrict__ Chi, __half* __restrict__ Clo)
{
    extern __shared__ char smem[];
    const uint32_t sb = smem_u32(smem);
    const int tid = threadIdx.x;
    const int wid = tid >> 5;
    const int lane = tid & 31;
    const int wm = wid >> 1;
    const int wn = wid & 1;
    const int m0 = blockIdx.y * 128, n0 = blockIdx.x * 64;

    const int lrow = tid >> 3;
    const int lkc = tid & 7;

    const uint32_t a_off = (uint32_t)((wm * 32 + (lane & 15)) * ROWB + (lane >> 4) * 16);
    const uint32_t b_off = (uint32_t)((wn * 32 + (lane & 15)) * ROWB + (lane >> 4) * 16);

    float acc[2][4][4];
#pragma unroll
    for (int i = 0; i < 2; i++)
#pragma unroll
        for (int j = 0; j < 4; j++)
#pragma unroll
            for (int r = 0; r < 4; r++) acc[i][j][r] = 0.0f;

#pragma unroll
    for (int q = 0; q < 4; q++) {
        int row = lrow + q * 32;
        cp_async16(sb + row * ROWB + lkc * 16,
                   (const char*)A + (size_t)(m0 + row) * 2048 + lkc * 16);
    }
#pragma unroll
    for (int q = 0; q < 2; q++) {
        int row = lrow + q * 32;
        cp_async16(sb + GB_OFF + row * ROWB + lkc * 16,
                   (const char*)B + (size_t)(n0 + row) * 2048 + lkc * 16);
    }
    cp_commit();

    for (int c = 0; c < 16; c++) {
        const uint32_t st = (uint32_t)(c & 1) * GSTAGE;
        if (c + 1 < 16) {
            const uint32_t st2 = (uint32_t)((c + 1) & 1) * GSTAGE;
            const size_t ko = (size_t)(c + 1) * 128;
#pragma unroll
            for (int q = 0; q < 4; q++) {
                int row = lrow + q * 32;
                cp_async16(st2 + sb + row * ROWB + lkc * 16,
                           (const char*)A + (size_t)(m0 + row) * 2048 + ko + lkc * 16);
            }
#pragma unroll
            for (int q = 0; q < 2; q++) {
                int row = lrow + q * 32;
                cp_async16(st2 + sb + GB_OFF + row * ROWB + lkc * 16,
                           (const char*)B + (size_t)(n0 + row) * 2048 + ko + lkc * 16);
            }
            cp_commit();
            cp_wait1();
        } else {
            cp_wait0();
        }
        __syncthreads();

#pragma unroll
        for (int kk = 0; kk < 4; kk++) {
            uint32_t bh[2][4];
#pragma unroll
            for (int p = 0; p < 2; p++) {
                uint32_t addr = st + sb + GB_OFF + b_off + (uint32_t)(p * 16 * ROWB) + kk * 32;
                ldsm4(bh[p][0], bh[p][1], bh[p][2], bh[p][3], addr);
            }
            uint32_t ah[2][4];
#pragma unroll
            for (int mf = 0; mf < 2; mf++) {
                uint32_t addr = st + sb + a_off + (uint32_t)(mf * 16 * ROWB) + kk * 32;
                ldsm4(ah[mf][0], ah[mf][1], ah[mf][2], ah[mf][3], addr);
            }
#pragma unroll
            for (int mf = 0; mf < 2; mf++)
#pragma unroll
                for (int nf = 0; nf < 4; nf++) {
                    const int p = nf >> 1, hh = nf & 1;
                    mma_f16(acc[mf][nf], ah[mf], bh[p][hh], bh[p][2 + hh]);
                }
        }
        __syncthreads();
    }

    // epilogue
#pragma unroll
    for (int nf = 0; nf < 4; nf++) {
        int n = n0 + wn * 32 + nf * 8 + (lane & 3) * 2;
        float2 bv = *(const float2*)(bias + n);
#pragma unroll
        for (int mf = 0; mf < 2; mf++) {
            int m = m0 + wm * 32 + mf * 16 + (lane >> 2);
            float2 o0 = {acc[mf][nf][0] + bv.x, acc[mf][nf][1] + bv.y};
            float2 o1 = {acc[mf][nf][2] + bv.x, acc[mf][nf][3] + bv.y};
            if (Chi) {
                size_t i0 = (size_t)m * 1024 + n;
                size_t i1 = (size_t)(m + 8) * 1024 + n;
                __half a0 = __float2half_rn(o0.x), a1 = __float2half_rn(o0.y);
                __half b0 = __float2half_rn(o1.x), b1 = __float2half_rn(o1.y);
                *(__half2*)(Chi + i0) = __halves2half2(a0, a1);
                *(__half2*)(Chi + i1) = __halves2half2(b0, b1);
                *(__half2*)(Clo + i0) = __halves2half2(
                    __float2half_rn(o0.x - __half2float(a0)),
                    __float2half_rn(o0.y - __half2float(a1)));
                *(__half2*)(Clo + i1) = __halves2half2(
                    __float2half_rn(o1.x - __half2float(b0)),
                    __float2half_rn(o1.y - __half2float(b1)));
            } else {
                *(float2*)(C + (size_t)m * 1024 + n) = o0;
                *(float2*)(C + (size_t)(m + 8) * 1024 + n) = o1;
            }
        }
    }
}

// ---------------- FA2-style attention -----------------------------------
// S = Qhi Khi^T (single term); P single fp16; O = P Vhi + P Vlo.
#define AK0 18432
#define AKST 36864
#define ATTN_SMEM_B (18432 + 2 * 36864)

__global__ __launch_bounds__(256, 2) void attn_mma(
    const __half* __restrict__ Khi, const __half* __restrict__ Klo,
    __half* __restrict__ Out)
{
    extern __shared__ char smem[];
    const uint32_t sb = smem_u32(smem);
    const int tid = threadIdx.x;
    const int wid = tid >> 5;
    const int lane = tid & 31;
    const int g = lane >> 2;
    const int tq = lane & 3;
    const int b = blockIdx.y >> 4;
    const int h = blockIdx.y & 15;
    const int q0 = blockIdx.x * 128;

    const char* KbH = (const char*)Khi + (size_t)b * 2048 * 2048 + h * 128;
    const char* KbL = (const char*)Klo + (size_t)b * 2048 * 2048 + h * 128;
    const float SC = 0.125f * 1.4426950408889634f;

    // prologue: Q tile (hi only) + K tile 0
#pragma unroll
    for (int q = 0; q < 4; q++) {
        int u = tid + q * 256;
        int row = u >> 3, c = u & 7;
        cp_async16(sb + row * ROWB + c * 16,
                   KbH + (size_t)(q0 + row) * 2048 + c * 16);
    }
#pragma unroll
    for (int q = 0; q < 4; q++) {
        int u = tid + q * 256;
        int row = u >> 3, c = u & 7;
        cp_async16(sb + AK0 + row * ROWB + c * 16, KbH + (size_t)row * 2048 + c * 16);
        cp_async16(sb + AK0 + 18432 + row * ROWB + c * 16,
                   KbL + (size_t)row * 2048 + c * 16);
    }
    cp_commit();

    float m0 = -1e30f, m1 = -1e30f, l0 = 0.0f, l1 = 0.0f;
    float o[8][4];
#pragma unroll
    for (int nf = 0; nf < 8; nf++)
#pragma unroll
        for (int r = 0; r < 4; r++) o[nf][r] = 0.0f;

    const uint32_t qa_off = (uint32_t)((wid * 16 + (lane & 15)) * ROWB + (lane >> 4) * 16);
    const uint32_t kb_row = (uint32_t)((lane & 15) * ROWB + (lane >> 4) * 16);

    for (int kt = 0; kt < 16; kt++) {
        const uint32_t st = sb + AK0 + (uint32_t)(kt & 1) * AKST;
        if (kt + 1 < 16) {
            const uint32_t st2 = sb + AK0 + (uint32_t)((kt + 1) & 1) * AKST;
            const size_t j0 = (size_t)(kt + 1) * 128;
#pragma unroll
            for (int q = 0; q < 4; q++) {
                int u = tid + q * 256;
                int row = u >> 3, c = u & 7;
                cp_async16(st2 + row * ROWB + c * 16, KbH + (j0 + row) * 2048 + c * 16);
                cp_async16(st2 + 18432 + row * ROWB + c * 16,
                           KbL + (j0 + row) * 2048 + c * 16);
            }
            cp_commit();
            cp_wait1();
        } else {
            cp_wait0();
        }
        __syncthreads();

        // ---- S = Qhi Khi^T (single term) ----
        float s[16][4];
#pragma unroll
        for (int nf = 0; nf < 16; nf++)
#pragma unroll
            for (int r = 0; r < 4; r++) s[nf][r] = 0.0f;

#pragma unroll
        for (int kk = 0; kk < 4; kk++) {
            uint32_t qh[4];
            ldsm4(qh[0], qh[1], qh[2], qh[3], sb + qa_off + kk * 32);
#pragma unroll
            for (int nb = 0; nb < 8; nb++) {
                uint32_t kh[4];
                uint32_t addr = st + kb_row + (uint32_t)(nb * 16 * ROWB) + kk * 32;
                ldsm4(kh[0], kh[1], kh[2], kh[3], addr);
#pragma unroll
                for (int hh = 0; hh < 2; hh++)
                    mma_f16(s[2 * nb + hh], qh, kh[hh], kh[2 + hh]);
            }
        }

        // ---- online softmax (scale folded) ----
        float mx0 = -1e30f, mx1 = -1e30f;
#pragma unroll
        for (int nf = 0; nf < 16; nf++) {
            mx0 = fmaxf(mx0, fmaxf(s[nf][0], s[nf][1]));
            mx1 = fmaxf(mx1, fmaxf(s[nf][2], s[nf][3]));
        }
        mx0 = fmaxf(mx0, __shfl_xor_sync(0xffffffffu, mx0, 1));
        mx0 = fmaxf(mx0, __shfl_xor_sync(0xffffffffu, mx0, 2));
        mx1 = fmaxf(mx1, __shfl_xor_sync(0xffffffffu, mx1, 1));
        mx1 = fmaxf(mx1, __shfl_xor_sync(0xffffffffu, mx1, 2));
        float mn0 = fmaxf(m0, mx0), mn1 = fmaxf(m1, mx1);
        float c0 = fast_exp2((m0 - mn0) * SC), c1 = fast_exp2((m1 - mn1) * SC);
        m0 = mn0; m1 = mn1;
        l0 *= c0; l1 *= c1;
#pragma unroll
        for (int nf = 0; nf < 8; nf++) {
            o[nf][0] *= c0; o[nf][1] *= c0;
            o[nf][2] *= c1; o[nf][3] *= c1;
        }
        const float b0s = -mn0 * SC, b1s = -mn1 * SC;
        float rs0 = 0.0f, rs1 = 0.0f;
#pragma unroll
        for (int nf = 0; nf < 16; nf++) {
            s[nf][0] = fast_exp2(fmaf(s[nf][0], SC, b0s));
            s[nf][1] = fast_exp2(fmaf(s[nf][1], SC, b0s));
            s[nf][2] = fast_exp2(fmaf(s[nf][2], SC, b1s));
            s[nf][3] = fast_exp2(fmaf(s[nf][3], SC, b1s));
            rs0 += s[nf][0] + s[nf][1];
            rs1 += s[nf][2] + s[nf][3];
        }
        rs0 += __shfl_xor_sync(0xffffffffu, rs0, 1);
        rs0 += __shfl_xor_sync(0xffffffffu, rs0, 2);
        rs1 += __shfl_xor_sync(0xffffffffu, rs1, 1);
        rs1 += __shfl_xor_sync(0xffffffffu, rs1, 2);
        l0 += rs0; l1 += rs1;

        // ---- O += P V (P single fp16; V hi + lo) ----
#pragma unroll
        for (int t = 0; t < 8; t++) {
            uint32_t ph[4];
            ph[0] = pack_h2(s[2 * t][0], s[2 * t][1]);
            ph[1] = pack_h2(s[2 * t][2], s[2 * t][3]);
            ph[2] = pack_h2(s[2 * t + 1][0], s[2 * t + 1][1]);
            ph[3] = pack_h2(s[2 * t + 1][2], s[2 * t + 1][3]);
#pragma unroll
            for (int nb = 0; nb < 4; nb++) {
                uint32_t vh[4], vl[4];
                uint32_t addr = st + kb_row + (uint32_t)(t * 16 * ROWB) + nb * 32;
                ldsm4t(vh[0], vh[1], vh[2], vh[3], addr);
                ldsm4t(vl[0], vl[1], vl[2], vl[3], addr + 18432);
#pragma unroll
                for (int hh = 0; hh < 2; hh++) {
                    mma_f16(o[2 * nb + hh], ph, vh[2 * hh], vh[2 * hh + 1]);
                    mma_f16(o[2 * nb + hh], ph, vl[2 * hh], vl[2 * hh + 1]);
                }
            }
        }
        __syncthreads();
    }

    // ---- epilogue ----
    float inv0 = 1.0f / l0, inv1 = 1.0f / l1;
    int mr0 = q0 + wid * 16 + g;
#pragma unroll
    for (int nf = 0; nf < 8; nf++) {
        int d = h * 64 + nf * 8 + tq * 2;
        size_t i0 = ((size_t)b * 2048 + mr0) * 1024 + d;
        size_t i1 = i0 + 8 * 1024;
        *(__half2*)(Out + i0) = __float22half2_rn(
            make_float2(o[nf][0] * inv0, o[nf][1] * inv0));
        *(__half2*)(Out + i1) = __float22half2_rn(
            make_float2(o[nf][2] * inv1, o[nf][3] * inv1));
    }
}

// ---------------------------------------------------------------------------
extern "C" void kernel_launch(void* const* d_in, const int* in_sizes, int n_in,
                              void* d_out, int out_size) {
    const float* x      = (const float*)d_in[0];  // (2, 2048, 1024)
    const float* W_attn = (const float*)d_in[1];  // (1024, 3072)
    const float* b_attn = (const float*)d_in[2];  // (3072,)
    const float* W_proj = (const float*)d_in[3];  // (1024, 1024)
    const float* b_proj = (const float*)d_in[4];  // (1024,)
    float* out = (float*)d_out;                   // (2, 2048, 1024)

    __half *xs, *ks_hi, *ks_lo, *att, *wk, *wp;
    cudaGetSymbolAddress((void**)&xs, g_xs);
    cudaGetSymbolAddress((void**)&ks_hi, g_ks_hi);
    cudaGetSymbolAddress((void**)&ks_lo, g_ks_lo);
    cudaGetSymbolAddress((void**)&att, g_att);
    cudaGetSymbolAddress((void**)&wk, g_wk);
    cudaGetSymbolAddress((void**)&wp, g_wp);

    const int GEMM_SMEM = 2 * GSTAGE;  // 55296
    cudaFuncSetAttribute(gemm_mma,
                         cudaFuncAttributeMaxDynamicSharedMemorySize, GEMM_SMEM);
    cudaFuncSetAttribute(attn_mma,
                         cudaFuncAttributeMaxDynamicSharedMemorySize, ATTN_SMEM_B);

    // Prep (one launch): x->fp16, W_attn K-slice and W_proj transposed fp16
    prep_kernel<<<6144, 256>>>(x, xs, W_attn + 1024, W_proj, wk, wp);

    // Stage 1: K = x @ W_attn[:, D:2D] + b  -> fp16 hi/lo split output
    gemm_mma<<<dim3(16, 32), 256, GEMM_SMEM>>>(xs, wk, b_attn + 1024,
                                               nullptr, ks_hi, ks_lo);

    // Stage 2: FA2 attention -> att single fp16
    attn_mma<<<dim3(16, 32), 256, ATTN_SMEM_B>>>(ks_hi, ks_lo, att);

    // Stage 3: out = att @ W_proj + b_proj (fp32 out)
    gemm_mma<<<dim3(16, 32), 256, GEMM_SMEM>>>(att, wp, b_proj,
                                               out, nullptr, nullptr);
}

// round 11
// speedup vs baseline: 2.3899x; 1.1390x over previous
#include <cuda_runtime.h>
#include <cuda_fp16.h>
#include <cstdint>

// ---------------- scratch (__device__ globals; no allocation allowed) -------
__device__ __half g_xs[4096 * 1024];            // x as fp16
__device__ __half g_ks[4096 * 1024];            // K projection fp16
__device__ __half g_att[4096 * 1024];           // attention out fp16
__device__ __half g_wk[1024 * 1024];            // W_attn K-slice, [n][k] fp16
__device__ __half g_wp[1024 * 1024];            // W_proj, [n][k] fp16

// ---------------- PTX helpers (all compute_103-safe) ------------------------
__device__ __forceinline__ float fast_exp2(float x) {
    float y; asm("ex2.approx.ftz.f32 %0, %1;" : "=f"(y) : "f"(x)); return y;
}
__device__ __forceinline__ uint32_t smem_u32(const void* p) {
    uint32_t a;
    asm("{ .reg .u64 t; cvta.to.shared.u64 t, %1; cvt.u32.u64 %0, t; }" : "=r"(a) : "l"(p));
    return a;
}
__device__ __forceinline__ void cp_async16(uint32_t dst, const void* src) {
    asm volatile("cp.async.cg.shared.global [%0], [%1], 16;" :: "r"(dst), "l"(src));
}
__device__ __forceinline__ void cp_commit() {
    asm volatile("cp.async.commit_group;" ::: "memory");
}
__device__ __forceinline__ void cp_wait1() {
    asm volatile("cp.async.wait_group 1;" ::: "memory");
}
__device__ __forceinline__ void cp_wait0() {
    asm volatile("cp.async.wait_group 0;" ::: "memory");
}
__device__ __forceinline__ void ldsm4(uint32_t& r0, uint32_t& r1, uint32_t& r2,
                                      uint32_t& r3, uint32_t addr) {
    asm volatile("ldmatrix.sync.aligned.m8n8.x4.shared.b16 {%0,%1,%2,%3}, [%4];"
                 : "=r"(r0), "=r"(r1), "=r"(r2), "=r"(r3) : "r"(addr));
}
__device__ __forceinline__ void ldsm4t(uint32_t& r0, uint32_t& r1, uint32_t& r2,
                                       uint32_t& r3, uint32_t addr) {
    asm volatile("ldmatrix.sync.aligned.m8n8.x4.trans.shared.b16 {%0,%1,%2,%3}, [%4];"
                 : "=r"(r0), "=r"(r1), "=r"(r2), "=r"(r3) : "r"(addr));
}
__device__ __forceinline__ void mma_f16(float* c, const uint32_t* a,
                                        uint32_t b0, uint32_t b1) {
    asm volatile(
        "mma.sync.aligned.m16n8k16.row.col.f32.f16.f16.f32 "
        "{%0,%1,%2,%3}, {%4,%5,%6,%7}, {%8,%9}, {%0,%1,%2,%3};"
        : "+f"(c[0]), "+f"(c[1]), "+f"(c[2]), "+f"(c[3])
        : "r"(a[0]), "r"(a[1]), "r"(a[2]), "r"(a[3]), "r"(b0), "r"(b1));
}
__device__ __forceinline__ uint32_t pack_h2(float a, float b) {
    __half2 h = __float22half2_rn(make_float2(a, b));
    return *(uint32_t*)&h;
}

// ---------------- merged prep: x->fp16; W transposes (single fp16) ----------
__global__ __launch_bounds__(256) void prep_kernel(
    const float* __restrict__ X, __half* __restrict__ XO,
    const float* __restrict__ Wk, const float* __restrict__ Wp,
    __half* __restrict__ WkO, __half* __restrict__ WpO)
{
    __shared__ float t[32][33];
    int bid = blockIdx.x;
    if (bid < 4096) {
        int i = bid * 256 + threadIdx.x;
        float4 v = ((const float4*)X)[i];
        ((__half2*)XO)[i * 2]     = __float22half2_rn(make_float2(v.x, v.y));
        ((__half2*)XO)[i * 2 + 1] = __float22half2_rn(make_float2(v.z, v.w));
        return;
    }
    bid -= 4096;
    const float* W; __half* O; int ldw;
    if (bid < 1024) { W = Wk; ldw = 3072; O = WkO; }
    else { bid -= 1024; W = Wp; ldw = 1024; O = WpO; }
    int n0 = (bid & 31) * 32, k0 = (bid >> 5) * 32;
    int tx = threadIdx.x & 31, ty = threadIdx.x >> 5;
#pragma unroll
    for (int p = 0; p < 4; p++)
        t[ty + 8 * p][tx] = W[(size_t)(k0 + ty + 8 * p) * ldw + n0 + tx];
    __syncthreads();
#pragma unroll
    for (int p = 0; p < 4; p++)
        O[(size_t)(n0 + ty + 8 * p) * 1024 + k0 + tx] =
            __float2half_rn(t[tx][ty + 8 * p]);
}

// ---------------- tensor-core GEMM: C = A @ B^T + bias (single fp16) --------
// Tile M=128, N=128, BK=64, 8 warps (4m x 2n, warp 32x64), double-buffered.
#define ROWB 144
#define GB_OFF 18432
#define GSTAGE 36864

__global__ __launch_bounds__(256) void gemm_mma(
    const __half* __restrict__ A, const __half* __restrict__ B,
    const float* __restrict__ bias, float* __restrict__ C,
    __half* __restrict__ Ch)
{
    extern __shared__ char smem[];
    const uint32_t sb = smem_u32(smem);
    const int tid = threadIdx.x;
    const int wid = tid >> 5;
    const int lane = tid & 31;
    const int wm = wid >> 1;        // 0..3, 32 rows
    const int wn = wid & 1;         // 0..1, 64 cols
    const int m0 = blockIdx.y * 128, n0 = blockIdx.x * 128;

    const int lrow = tid >> 1;              // 0..127
    const int lkc = (tid & 1) * 4;          // 4 consecutive 16B units

    const uint32_t a_off = (uint32_t)((wm * 32 + (lane & 15)) * ROWB + (lane >> 4) * 16);
    const uint32_t b_off = (uint32_t)((wn * 64 + (lane & 15)) * ROWB + (lane >> 4) * 16);

    float acc[2][8][4];
#pragma unroll
    for (int i = 0; i < 2; i++)
#pragma unroll
        for (int j = 0; j < 8; j++)
#pragma unroll
            for (int r = 0; r < 4; r++) acc[i][j][r] = 0.0f;

    // prologue: chunk 0 -> stage 0  (A and B tiles are 128 rows x 8 units)
#pragma unroll
    for (int u = 0; u < 4; u++) {
        cp_async16(sb + lrow * ROWB + (lkc + u) * 16,
                   (const char*)A + (size_t)(m0 + lrow) * 2048 + (lkc + u) * 16);
    }
#pragma unroll
    for (int u = 0; u < 4; u++) {
        cp_async16(sb + GB_OFF + lrow * ROWB + (lkc + u) * 16,
                   (const char*)B + (size_t)(n0 + lrow) * 2048 + (lkc + u) * 16);
    }
    cp_commit();

    for (int c = 0; c < 16; c++) {
        const uint32_t st = (uint32_t)(c & 1) * GSTAGE;
        if (c + 1 < 16) {
            const uint32_t st2 = (uint32_t)((c + 1) & 1) * GSTAGE;
            const size_t ko = (size_t)(c + 1) * 128;
#pragma unroll
            for (int u = 0; u < 4; u++) {
                cp_async16(st2 + sb + lrow * ROWB + (lkc + u) * 16,
                           (const char*)A + (size_t)(m0 + lrow) * 2048 + ko + (lkc + u) * 16);
            }
#pragma unroll
            for (int u = 0; u < 4; u++) {
                cp_async16(st2 + sb + GB_OFF + lrow * ROWB + (lkc + u) * 16,
                           (const char*)B + (size_t)(n0 + lrow) * 2048 + ko + (lkc + u) * 16);
            }
            cp_commit();
            cp_wait1();
        } else {
            cp_wait0();
        }
        __syncthreads();

#pragma unroll
        for (int kk = 0; kk < 4; kk++) {
            uint32_t bh[4][4];
#pragma unroll
            for (int p = 0; p < 4; p++) {
                uint32_t addr = st + sb + GB_OFF + b_off + (uint32_t)(p * 16 * ROWB) + kk * 32;
                ldsm4(bh[p][0], bh[p][1], bh[p][2], bh[p][3], addr);
            }
            uint32_t ah[2][4];
#pragma unroll
            for (int mf = 0; mf < 2; mf++) {
                uint32_t addr = st + sb + a_off + (uint32_t)(mf * 16 * ROWB) + kk * 32;
                ldsm4(ah[mf][0], ah[mf][1], ah[mf][2], ah[mf][3], addr);
            }
#pragma unroll
            for (int mf = 0; mf < 2; mf++)
#pragma unroll
                for (int nf = 0; nf < 8; nf++) {
                    const int p = nf >> 1, hh = nf & 1;
                    mma_f16(acc[mf][nf], ah[mf], bh[p][hh], bh[p][2 + hh]);
                }
        }
        __syncthreads();
    }

    // epilogue
#pragma unroll
    for (int nf = 0; nf < 8; nf++) {
        int n = n0 + wn * 64 + nf * 8 + (lane & 3) * 2;
        float2 bv = *(const float2*)(bias + n);
#pragma unroll
        for (int mf = 0; mf < 2; mf++) {
            int m = m0 + wm * 32 + mf * 16 + (lane >> 2);
            float2 o0 = {acc[mf][nf][0] + bv.x, acc[mf][nf][1] + bv.y};
            float2 o1 = {acc[mf][nf][2] + bv.x, acc[mf][nf][3] + bv.y};
            if (Ch) {
                *(__half2*)(Ch + (size_t)m * 1024 + n) =
                    __float22half2_rn(make_float2(o0.x, o0.y));
                *(__half2*)(Ch + (size_t)(m + 8) * 1024 + n) =
                    __float22half2_rn(make_float2(o1.x, o1.y));
            } else {
                *(float2*)(C + (size_t)m * 1024 + n) = o0;
                *(float2*)(C + (size_t)(m + 8) * 1024 + n) = o1;
            }
        }
    }
}

// ---------------- FA2-style attention (single-fp16 K throughout) ------------
// S = Q K^T; P fp16; O = P V, with Q == V == K tile (fp16).
#define AK0 18432
#define AKST 18432
#define ATTN_SMEM_B (18432 + 2 * 18432)

__global__ __launch_bounds__(256, 2) void attn_mma(
    const __half* __restrict__ K, __half* __restrict__ Out)
{
    extern __shared__ char smem[];
    const uint32_t sb = smem_u32(smem);
    const int tid = threadIdx.x;
    const int wid = tid >> 5;
    const int lane = tid & 31;
    const int g = lane >> 2;
    const int tq = lane & 3;
    const int b = blockIdx.y >> 4;
    const int h = blockIdx.y & 15;
    const int q0 = blockIdx.x * 128;

    const char* Kb = (const char*)K + (size_t)b * 2048 * 2048 + h * 128;
    const float SC = 0.125f * 1.4426950408889634f;

    // prologue: Q tile + K tile 0
#pragma unroll
    for (int q = 0; q < 4; q++) {
        int u = tid + q * 256;
        int row = u >> 3, c = u & 7;
        cp_async16(sb + row * ROWB + c * 16,
                   Kb + (size_t)(q0 + row) * 2048 + c * 16);
    }
#pragma unroll
    for (int q = 0; q < 4; q++) {
        int u = tid + q * 256;
        int row = u >> 3, c = u & 7;
        cp_async16(sb + AK0 + row * ROWB + c * 16, Kb + (size_t)row * 2048 + c * 16);
    }
    cp_commit();

    float m0 = -1e30f, m1 = -1e30f, l0 = 0.0f, l1 = 0.0f;
    float o[8][4];
#pragma unroll
    for (int nf = 0; nf < 8; nf++)
#pragma unroll
        for (int r = 0; r < 4; r++) o[nf][r] = 0.0f;

    const uint32_t qa_off = (uint32_t)((wid * 16 + (lane & 15)) * ROWB + (lane >> 4) * 16);
    const uint32_t kb_row = (uint32_t)((lane & 15) * ROWB + (lane >> 4) * 16);

    for (int kt = 0; kt < 16; kt++) {
        const uint32_t st = sb + AK0 + (uint32_t)(kt & 1) * AKST;
        if (kt + 1 < 16) {
            const uint32_t st2 = sb + AK0 + (uint32_t)((kt + 1) & 1) * AKST;
            const size_t j0 = (size_t)(kt + 1) * 128;
#pragma unroll
            for (int q = 0; q < 4; q++) {
                int u = tid + q * 256;
                int row = u >> 3, c = u & 7;
                cp_async16(st2 + row * ROWB + c * 16, Kb + (j0 + row) * 2048 + c * 16);
            }
            cp_commit();
            cp_wait1();
        } else {
            cp_wait0();
        }
        __syncthreads();

        // ---- S = Q K^T ----
        float s[16][4];
#pragma unroll
        for (int nf = 0; nf < 16; nf++)
#pragma unroll
            for (int r = 0; r < 4; r++) s[nf][r] = 0.0f;

#pragma unroll
        for (int kk = 0; kk < 4; kk++) {
            uint32_t qh[4];
            ldsm4(qh[0], qh[1], qh[2], qh[3], sb + qa_off + kk * 32);
#pragma unroll
            for (int nb = 0; nb < 8; nb++) {
                uint32_t kh[4];
                uint32_t addr = st + kb_row + (uint32_t)(nb * 16 * ROWB) + kk * 32;
                ldsm4(kh[0], kh[1], kh[2], kh[3], addr);
#pragma unroll
                for (int hh = 0; hh < 2; hh++)
                    mma_f16(s[2 * nb + hh], qh, kh[hh], kh[2 + hh]);
            }
        }

        // ---- online softmax (scale folded) ----
        float mx0 = -1e30f, mx1 = -1e30f;
#pragma unroll
        for (int nf = 0; nf < 16; nf++) {
            mx0 = fmaxf(mx0, fmaxf(s[nf][0], s[nf][1]));
            mx1 = fmaxf(mx1, fmaxf(s[nf][2], s[nf][3]));
        }
        mx0 = fmaxf(mx0, __shfl_xor_sync(0xffffffffu, mx0, 1));
        mx0 = fmaxf(mx0, __shfl_xor_sync(0xffffffffu, mx0, 2));
        mx1 = fmaxf(mx1, __shfl_xor_sync(0xffffffffu, mx1, 1));
        mx1 = fmaxf(mx1, __shfl_xor_sync(0xffffffffu, mx1, 2));
        float mn0 = fmaxf(m0, mx0), mn1 = fmaxf(m1, mx1);
        float c0 = fast_exp2((m0 - mn0) * SC), c1 = fast_exp2((m1 - mn1) * SC);
        m0 = mn0; m1 = mn1;
        l0 *= c0; l1 *= c1;
#pragma unroll
        for (int nf = 0; nf < 8; nf++) {
            o[nf][0] *= c0; o[nf][1] *= c0;
            o[nf][2] *= c1; o[nf][3] *= c1;
        }
        const float b0s = -mn0 * SC, b1s = -mn1 * SC;
        float rs0 = 0.0f, rs1 = 0.0f;
#pragma unroll
        for (int nf = 0; nf < 16; nf++) {
            s[nf][0] = fast_exp2(fmaf(s[nf][0], SC, b0s));
            s[nf][1] = fast_exp2(fmaf(s[nf][1], SC, b0s));
            s[nf][2] = fast_exp2(fmaf(s[nf][2], SC, b1s));
            s[nf][3] = fast_exp2(fmaf(s[nf][3], SC, b1s));
            rs0 += s[nf][0] + s[nf][1];
            rs1 += s[nf][2] + s[nf][3];
        }
        rs0 += __shfl_xor_sync(0xffffffffu, rs0, 1);
        rs0 += __shfl_xor_sync(0xffffffffu, rs0, 2);
        rs1 += __shfl_xor_sync(0xffffffffu, rs1, 1);
        rs1 += __shfl_xor_sync(0xffffffffu, rs1, 2);
        l0 += rs0; l1 += rs1;

        // ---- O += P V (single term; V via ldsm.trans) ----
#pragma unroll
        for (int t = 0; t < 8; t++) {
            uint32_t ph[4];
            ph[0] = pack_h2(s[2 * t][0], s[2 * t][1]);
            ph[1] = pack_h2(s[2 * t][2], s[2 * t][3]);
            ph[2] = pack_h2(s[2 * t + 1][0], s[2 * t + 1][1]);
            ph[3] = pack_h2(s[2 * t + 1][2], s[2 * t + 1][3]);
#pragma unroll
            for (int nb = 0; nb < 4; nb++) {
                uint32_t vh[4];
                uint32_t addr = st + kb_row + (uint32_t)(t * 16 * ROWB) + nb * 32;
                ldsm4t(vh[0], vh[1], vh[2], vh[3], addr);
#pragma unroll
                for (int hh = 0; hh < 2; hh++)
                    mma_f16(o[2 * nb + hh], ph, vh[2 * hh], vh[2 * hh + 1]);
            }
        }
        __syncthreads();
    }

    // ---- epilogue ----
    float inv0 = 1.0f / l0, inv1 = 1.0f / l1;
    int mr0 = q0 + wid * 16 + g;
#pragma unroll
    for (int nf = 0; nf < 8; nf++) {
        int d = h * 64 + nf * 8 + tq * 2;
        size_t i0 = ((size_t)b * 2048 + mr0) * 1024 + d;
        size_t i1 = i0 + 8 * 1024;
        *(__half2*)(Out + i0) = __float22half2_rn(
            make_float2(o[nf][0] * inv0, o[nf][1] * inv0));
        *(__half2*)(Out + i1) = __float22half2_rn(
            make_float2(o[nf][2] * inv1, o[nf][3] * inv1));
    }
}

// ---------------------------------------------------------------------------
extern "C" void kernel_launch(void* const* d_in, const int* in_sizes, int n_in,
                              void* d_out, int out_size) {
    const float* x      = (const float*)d_in[0];  // (2, 2048, 1024)
    const float* W_attn = (const float*)d_in[1];  // (1024, 3072)
    const float* b_attn = (const float*)d_in[2];  // (3072,)
    const float* W_proj = (const float*)d_in[3];  // (1024, 1024)
    const float* b_proj = (const float*)d_in[4];  // (1024,)
    float* out = (float*)d_out;                   // (2, 2048, 1024)

    __half *xs, *ks, *att, *wk, *wp;
    cudaGetSymbolAddress((void**)&xs, g_xs);
    cudaGetSymbolAddress((void**)&ks, g_ks);
    cudaGetSymbolAddress((void**)&att, g_att);
    cudaGetSymbolAddress((void**)&wk, g_wk);
    cudaGetSymbolAddress((void**)&wp, g_wp);

    const int GEMM_SMEM = 2 * GSTAGE;  // 73728
    cudaFuncSetAttribute(gemm_mma,
                         cudaFuncAttributeMaxDynamicSharedMemorySize, GEMM_SMEM);
    cudaFuncSetAttribute(attn_mma,
                         cudaFuncAttributeMaxDynamicSharedMemorySize, ATTN_SMEM_B);

    // Prep (one launch)
    prep_kernel<<<6144, 256>>>(x, xs, W_attn + 1024, W_proj, wk, wp);

    // Stage 1: K = x @ W_attn[:, D:2D] + b  -> single fp16
    gemm_mma<<<dim3(8, 32), 256, GEMM_SMEM>>>(xs, wk, b_attn + 1024, nullptr, ks);

    // Stage 2: FA2 attention -> att fp16
    attn_mma<<<dim3(16, 32), 256, ATTN_SMEM_B>>>(ks, att);

    // Stage 3: out = att @ W_proj + b_proj (fp32 out)
    gemm_mma<<<dim3(8, 32), 256, GEMM_SMEM>>>(att, wp, b_proj, out, nullptr);
}

// round 12
// speedup vs baseline: 2.6487x; 1.1083x over previous
#include <cuda_runtime.h>
#include <cuda_fp16.h>
#include <cstdint>

// ---------------- scratch (__device__ globals; no allocation allowed) -------
__device__ __half g_xs[4096 * 1024];            // x as fp16
__device__ __half g_ks[4096 * 1024];            // K projection fp16
__device__ __half g_att[4096 * 1024];           // attention out fp16
__device__ __half g_wk[1024 * 1024];            // W_attn K-slice, [n][k] fp16
__device__ __half g_wp[1024 * 1024];            // W_proj, [n][k] fp16

// ---------------- PTX helpers (all compute_103-safe) ------------------------
__device__ __forceinline__ float fast_exp2(float x) {
    float y; asm("ex2.approx.ftz.f32 %0, %1;" : "=f"(y) : "f"(x)); return y;
}
__device__ __forceinline__ uint32_t smem_u32(const void* p) {
    uint32_t a;
    asm("{ .reg .u64 t; cvta.to.shared.u64 t, %1; cvt.u32.u64 %0, t; }" : "=r"(a) : "l"(p));
    return a;
}
__device__ __forceinline__ void cp_async16(uint32_t dst, const void* src) {
    asm volatile("cp.async.cg.shared.global [%0], [%1], 16;" :: "r"(dst), "l"(src));
}
__device__ __forceinline__ void cp_commit() {
    asm volatile("cp.async.commit_group;" ::: "memory");
}
__device__ __forceinline__ void cp_wait1() {
    asm volatile("cp.async.wait_group 1;" ::: "memory");
}
__device__ __forceinline__ void cp_wait0() {
    asm volatile("cp.async.wait_group 0;" ::: "memory");
}
__device__ __forceinline__ void ldsm4(uint32_t& r0, uint32_t& r1, uint32_t& r2,
                                      uint32_t& r3, uint32_t addr) {
    asm volatile("ldmatrix.sync.aligned.m8n8.x4.shared.b16 {%0,%1,%2,%3}, [%4];"
                 : "=r"(r0), "=r"(r1), "=r"(r2), "=r"(r3) : "r"(addr));
}
__device__ __forceinline__ void ldsm4t(uint32_t& r0, uint32_t& r1, uint32_t& r2,
                                       uint32_t& r3, uint32_t addr) {
    asm volatile("ldmatrix.sync.aligned.m8n8.x4.trans.shared.b16 {%0,%1,%2,%3}, [%4];"
                 : "=r"(r0), "=r"(r1), "=r"(r2), "=r"(r3) : "r"(addr));
}
__device__ __forceinline__ void mma_f16(float* c, const uint32_t* a,
                                        uint32_t b0, uint32_t b1) {
    asm volatile(
        "mma.sync.aligned.m16n8k16.row.col.f32.f16.f16.f32 "
        "{%0,%1,%2,%3}, {%4,%5,%6,%7}, {%8,%9}, {%0,%1,%2,%3};"
        : "+f"(c[0]), "+f"(c[1]), "+f"(c[2]), "+f"(c[3])
        : "r"(a[0]), "r"(a[1]), "r"(a[2]), "r"(a[3]), "r"(b0), "r"(b1));
}
__device__ __forceinline__ uint32_t pack_h2(float a, float b) {
    __half2 h = __float22half2_rn(make_float2(a, b));
    return *(uint32_t*)&h;
}

// ---------------- merged prep: x->fp16; W transposes (single fp16) ----------
__global__ __launch_bounds__(256) void prep_kernel(
    const float* __restrict__ X, __half* __restrict__ XO,
    const float* __restrict__ Wk, const float* __restrict__ Wp,
    __half* __restrict__ WkO, __half* __restrict__ WpO)
{
    __shared__ float t[32][33];
    int bid = blockIdx.x;
    if (bid < 4096) {
        int i = bid * 256 + threadIdx.x;
        float4 v = ((const float4*)X)[i];
        ((__half2*)XO)[i * 2]     = __float22half2_rn(make_float2(v.x, v.y));
        ((__half2*)XO)[i * 2 + 1] = __float22half2_rn(make_float2(v.z, v.w));
        return;
    }
    bid -= 4096;
    const float* W; __half* O; int ldw;
    if (bid < 1024) { W = Wk; ldw = 3072; O = WkO; }
    else { bid -= 1024; W = Wp; ldw = 1024; O = WpO; }
    int n0 = (bid & 31) * 32, k0 = (bid >> 5) * 32;
    int tx = threadIdx.x & 31, ty = threadIdx.x >> 5;
#pragma unroll
    for (int p = 0; p < 4; p++)
        t[ty + 8 * p][tx] = W[(size_t)(k0 + ty + 8 * p) * ldw + n0 + tx];
    __syncthreads();
#pragma unroll
    for (int p = 0; p < 4; p++)
        O[(size_t)(n0 + ty + 8 * p) * 1024 + k0 + tx] =
            __float2half_rn(t[tx][ty + 8 * p]);
}

// ---------------- tensor-core GEMM: C = A @ B^T + bias (single fp16) --------
// Tile M=128, N=64, BK=64, 8 warps (4m x 2n, warp 32x32), double-buffered.
// (Measured-best R10 configuration.)
#define ROWB 144
#define GB_OFF 18432
#define GSTAGE 27648

__global__ __launch_bounds__(256, 3) void gemm_mma(
    const __half* __restrict__ A, const __half* __restrict__ B,
    const float* __restrict__ bias, float* __restrict__ C,
    __half* __restrict__ Ch)
{
    extern __shared__ char smem[];
    const uint32_t sb = smem_u32(smem);
    const int tid = threadIdx.x;
    const int wid = tid >> 5;
    const int lane = tid & 31;
    const int wm = wid >> 1;
    const int wn = wid & 1;
    const int m0 = blockIdx.y * 128, n0 = blockIdx.x * 64;

    const int lrow = tid >> 3;
    const int lkc = tid & 7;

    const uint32_t a_off = (uint32_t)((wm * 32 + (lane & 15)) * ROWB + (lane >> 4) * 16);
    const uint32_t b_off = (uint32_t)((wn * 32 + (lane & 15)) * ROWB + (lane >> 4) * 16);

    float acc[2][4][4];
#pragma unroll
    for (int i = 0; i < 2; i++)
#pragma unroll
        for (int j = 0; j < 4; j++)
#pragma unroll
            for (int r = 0; r < 4; r++) acc[i][j][r] = 0.0f;

#pragma unroll
    for (int q = 0; q < 4; q++) {
        int row = lrow + q * 32;
        cp_async16(sb + row * ROWB + lkc * 16,
                   (const char*)A + (size_t)(m0 + row) * 2048 + lkc * 16);
    }
#pragma unroll
    for (int q = 0; q < 2; q++) {
        int row = lrow + q * 32;
        cp_async16(sb + GB_OFF + row * ROWB + lkc * 16,
                   (const char*)B + (size_t)(n0 + row) * 2048 + lkc * 16);
    }
    cp_commit();

    for (int c = 0; c < 16; c++) {
        const uint32_t st = (uint32_t)(c & 1) * GSTAGE;
        if (c + 1 < 16) {
            const uint32_t st2 = (uint32_t)((c + 1) & 1) * GSTAGE;
            const size_t ko = (size_t)(c + 1) * 128;
#pragma unroll
            for (int q = 0; q < 4; q++) {
                int row = lrow + q * 32;
                cp_async16(st2 + sb + row * ROWB + lkc * 16,
                           (const char*)A + (size_t)(m0 + row) * 2048 + ko + lkc * 16);
            }
#pragma unroll
            for (int q = 0; q < 2; q++) {
                int row = lrow + q * 32;
                cp_async16(st2 + sb + GB_OFF + row * ROWB + lkc * 16,
                           (const char*)B + (size_t)(n0 + row) * 2048 + ko + lkc * 16);
            }
            cp_commit();
            cp_wait1();
        } else {
            cp_wait0();
        }
        __syncthreads();

#pragma unroll
        for (int kk = 0; kk < 4; kk++) {
            uint32_t bh[2][4];
#pragma unroll
            for (int p = 0; p < 2; p++) {
                uint32_t addr = st + sb + GB_OFF + b_off + (uint32_t)(p * 16 * ROWB) + kk * 32;
                ldsm4(bh[p][0], bh[p][1], bh[p][2], bh[p][3], addr);
            }
            uint32_t ah[2][4];
#pragma unroll
            for (int mf = 0; mf < 2; mf++) {
                uint32_t addr = st + sb + a_off + (uint32_t)(mf * 16 * ROWB) + kk * 32;
                ldsm4(ah[mf][0], ah[mf][1], ah[mf][2], ah[mf][3], addr);
            }
#pragma unroll
            for (int mf = 0; mf < 2; mf++)
#pragma unroll
                for (int nf = 0; nf < 4; nf++) {
                    const int p = nf >> 1, hh = nf & 1;
                    mma_f16(acc[mf][nf], ah[mf], bh[p][hh], bh[p][2 + hh]);
                }
        }
        __syncthreads();
    }

    // epilogue
#pragma unroll
    for (int nf = 0; nf < 4; nf++) {
        int n = n0 + wn * 32 + nf * 8 + (lane & 3) * 2;
        float2 bv = *(const float2*)(bias + n);
#pragma unroll
        for (int mf = 0; mf < 2; mf++) {
            int m = m0 + wm * 32 + mf * 16 + (lane >> 2);
            float2 o0 = {acc[mf][nf][0] + bv.x, acc[mf][nf][1] + bv.y};
            float2 o1 = {acc[mf][nf][2] + bv.x, acc[mf][nf][3] + bv.y};
            if (Ch) {
                *(__half2*)(Ch + (size_t)m * 1024 + n) =
                    __float22half2_rn(make_float2(o0.x, o0.y));
                *(__half2*)(Ch + (size_t)(m + 8) * 1024 + n) =
                    __float22half2_rn(make_float2(o1.x, o1.y));
            } else {
                *(float2*)(C + (size_t)m * 1024 + n) = o0;
                *(float2*)(C + (size_t)(m + 8) * 1024 + n) = o1;
            }
        }
    }
}

// ---------------- FA2-style attention (single-fp16 K throughout) ------------
#define AK0 18432
#define AKST 18432
#define ATTN_SMEM_B (18432 + 2 * 18432)

__global__ __launch_bounds__(256, 2) void attn_mma(
    const __half* __restrict__ K, __half* __restrict__ Out)
{
    extern __shared__ char smem[];
    const uint32_t sb = smem_u32(smem);
    const int tid = threadIdx.x;
    const int wid = tid >> 5;
    const int lane = tid & 31;
    const int g = lane >> 2;
    const int tq = lane & 3;
    const int b = blockIdx.y >> 4;
    const int h = blockIdx.y & 15;
    const int q0 = blockIdx.x * 128;

    const char* Kb = (const char*)K + (size_t)b * 2048 * 2048 + h * 128;
    const float SC = 0.125f * 1.4426950408889634f;

#pragma unroll
    for (int q = 0; q < 4; q++) {
        int u = tid + q * 256;
        int row = u >> 3, c = u & 7;
        cp_async16(sb + row * ROWB + c * 16,
                   Kb + (size_t)(q0 + row) * 2048 + c * 16);
    }
#pragma unroll
    for (int q = 0; q < 4; q++) {
        int u = tid + q * 256;
        int row = u >> 3, c = u & 7;
        cp_async16(sb + AK0 + row * ROWB + c * 16, Kb + (size_t)row * 2048 + c * 16);
    }
    cp_commit();

    float m0 = -1e30f, m1 = -1e30f, l0 = 0.0f, l1 = 0.0f;
    float o[8][4];
#pragma unroll
    for (int nf = 0; nf < 8; nf++)
#pragma unroll
        for (int r = 0; r < 4; r++) o[nf][r] = 0.0f;

    const uint32_t qa_off = (uint32_t)((wid * 16 + (lane & 15)) * ROWB + (lane >> 4) * 16);
    const uint32_t kb_row = (uint32_t)((lane & 15) * ROWB + (lane >> 4) * 16);

    for (int kt = 0; kt < 16; kt++) {
        const uint32_t st = sb + AK0 + (uint32_t)(kt & 1) * AKST;
        if (kt + 1 < 16) {
            const uint32_t st2 = sb + AK0 + (uint32_t)((kt + 1) & 1) * AKST;
            const size_t j0 = (size_t)(kt + 1) * 128;
#pragma unroll
            for (int q = 0; q < 4; q++) {
                int u = tid + q * 256;
                int row = u >> 3, c = u & 7;
                cp_async16(st2 + row * ROWB + c * 16, Kb + (j0 + row) * 2048 + c * 16);
            }
            cp_commit();
            cp_wait1();
        } else {
            cp_wait0();
        }
        __syncthreads();

        // ---- S = Q K^T ----
        float s[16][4];
#pragma unroll
        for (int nf = 0; nf < 16; nf++)
#pragma unroll
            for (int r = 0; r < 4; r++) s[nf][r] = 0.0f;

#pragma unroll
        for (int kk = 0; kk < 4; kk++) {
            uint32_t qh[4];
            ldsm4(qh[0], qh[1], qh[2], qh[3], sb + qa_off + kk * 32);
#pragma unroll
            for (int nb = 0; nb < 8; nb++) {
                uint32_t kh[4];
                uint32_t addr = st + kb_row + (uint32_t)(nb * 16 * ROWB) + kk * 32;
                ldsm4(kh[0], kh[1], kh[2], kh[3], addr);
#pragma unroll
                for (int hh = 0; hh < 2; hh++)
                    mma_f16(s[2 * nb + hh], qh, kh[hh], kh[2 + hh]);
            }
        }

        // ---- online softmax (scale folded) ----
        float mx0 = -1e30f, mx1 = -1e30f;
#pragma unroll
        for (int nf = 0; nf < 16; nf++) {
            mx0 = fmaxf(mx0, fmaxf(s[nf][0], s[nf][1]));
            mx1 = fmaxf(mx1, fmaxf(s[nf][2], s[nf][3]));
        }
        mx0 = fmaxf(mx0, __shfl_xor_sync(0xffffffffu, mx0, 1));
        mx0 = fmaxf(mx0, __shfl_xor_sync(0xffffffffu, mx0, 2));
        mx1 = fmaxf(mx1, __shfl_xor_sync(0xffffffffu, mx1, 1));
        mx1 = fmaxf(mx1, __shfl_xor_sync(0xffffffffu, mx1, 2));
        float mn0 = fmaxf(m0, mx0), mn1 = fmaxf(m1, mx1);
        float c0 = fast_exp2((m0 - mn0) * SC), c1 = fast_exp2((m1 - mn1) * SC);
        m0 = mn0; m1 = mn1;
        l0 *= c0; l1 *= c1;
#pragma unroll
        for (int nf = 0; nf < 8; nf++) {
            o[nf][0] *= c0; o[nf][1] *= c0;
            o[nf][2] *= c1; o[nf][3] *= c1;
        }
        const float b0s = -mn0 * SC, b1s = -mn1 * SC;
        float rs0 = 0.0f, rs1 = 0.0f;
#pragma unroll
        for (int nf = 0; nf < 16; nf++) {
            s[nf][0] = fast_exp2(fmaf(s[nf][0], SC, b0s));
            s[nf][1] = fast_exp2(fmaf(s[nf][1], SC, b0s));
            s[nf][2] = fast_exp2(fmaf(s[nf][2], SC, b1s));
            s[nf][3] = fast_exp2(fmaf(s[nf][3], SC, b1s));
            rs0 += s[nf][0] + s[nf][1];
            rs1 += s[nf][2] + s[nf][3];
        }
        rs0 += __shfl_xor_sync(0xffffffffu, rs0, 1);
        rs0 += __shfl_xor_sync(0xffffffffu, rs0, 2);
        rs1 += __shfl_xor_sync(0xffffffffu, rs1, 1);
        rs1 += __shfl_xor_sync(0xffffffffu, rs1, 2);
        l0 += rs0; l1 += rs1;

        // ---- O += P V (single term; V via ldsm.trans) ----
#pragma unroll
        for (int t = 0; t < 8; t++) {
            uint32_t ph[4];
            ph[0] = pack_h2(s[2 * t][0], s[2 * t][1]);
            ph[1] = pack_h2(s[2 * t][2], s[2 * t][3]);
            ph[2] = pack_h2(s[2 * t + 1][0], s[2 * t + 1][1]);
            ph[3] = pack_h2(s[2 * t + 1][2], s[2 * t + 1][3]);
#pragma unroll
            for (int nb = 0; nb < 4; nb++) {
                uint32_t vh[4];
                uint32_t addr = st + kb_row + (uint32_t)(t * 16 * ROWB) + nb * 32;
                ldsm4t(vh[0], vh[1], vh[2], vh[3], addr);
#pragma unroll
                for (int hh = 0; hh < 2; hh++)
                    mma_f16(o[2 * nb + hh], ph, vh[2 * hh], vh[2 * hh + 1]);
            }
        }
        __syncthreads();
    }

    // ---- epilogue ----
    float inv0 = 1.0f / l0, inv1 = 1.0f / l1;
    int mr0 = q0 + wid * 16 + g;
#pragma unroll
    for (int nf = 0; nf < 8; nf++) {
        int d = h * 64 + nf * 8 + tq * 2;
        size_t i0 = ((size_t)b * 2048 + mr0) * 1024 + d;
        size_t i1 = i0 + 8 * 1024;
        *(__half2*)(Out + i0) = __float22half2_rn(
            make_float2(o[nf][0] * inv0, o[nf][1] * inv0));
        *(__half2*)(Out + i1) = __float22half2_rn(
            make_float2(o[nf][2] * inv1, o[nf][3] * inv1));
    }
}

// ---------------------------------------------------------------------------
extern "C" void kernel_launch(void* const* d_in, const int* in_sizes, int n_in,
                              void* d_out, int out_size) {
    const float* x      = (const float*)d_in[0];  // (2, 2048, 1024)
    const float* W_attn = (const float*)d_in[1];  // (1024, 3072)
    const float* b_attn = (const float*)d_in[2];  // (3072,)
    const float* W_proj = (const float*)d_in[3];  // (1024, 1024)
    const float* b_proj = (const float*)d_in[4];  // (1024,)
    float* out = (float*)d_out;                   // (2, 2048, 1024)

    __half *xs, *ks, *att, *wk, *wp;
    cudaGetSymbolAddress((void**)&xs, g_xs);
    cudaGetSymbolAddress((void**)&ks, g_ks);
    cudaGetSymbolAddress((void**)&att, g_att);
    cudaGetSymbolAddress((void**)&wk, g_wk);
    cudaGetSymbolAddress((void**)&wp, g_wp);

    const int GEMM_SMEM = 2 * GSTAGE;  // 55296
    cudaFuncSetAttribute(gemm_mma,
                         cudaFuncAttributeMaxDynamicSharedMemorySize, GEMM_SMEM);
    cudaFuncSetAttribute(attn_mma,
                         cudaFuncAttributeMaxDynamicSharedMemorySize, ATTN_SMEM_B);

    // Prep (one launch)
    prep_kernel<<<6144, 256>>>(x, xs, W_attn + 1024, W_proj, wk, wp);

    // Stage 1: K = x @ W_attn[:, D:2D] + b  -> single fp16
    gemm_mma<<<dim3(16, 32), 256, GEMM_SMEM>>>(xs, wk, b_attn + 1024, nullptr, ks);

    // Stage 2: FA2 attention -> att fp16
    attn_mma<<<dim3(16, 32), 256, ATTN_SMEM_B>>>(ks, att);

    // Stage 3: out = att @ W_proj + b_proj (fp32 out)
    gemm_mma<<<dim3(16, 32), 256, GEMM_SMEM>>>(att, wp, b_proj, out, nullptr);
}